// round 2
// baseline (speedup 1.0000x reference)
#include <cuda_runtime.h>
#include <math.h>

// Problem constants
#define BATCH 4
#define SEQ 2048
#define DMODEL 1024
#define NHEAD 16
#define DK 64
#define ROWS (BATCH * SEQ)   // 8192

// ---------------------------------------------------------------------------
// Scratch (device globals; no allocation allowed)
// ---------------------------------------------------------------------------
__device__ float g_x2[ROWS * DMODEL];
__device__ float g_q[ROWS * DMODEL];
__device__ float g_k[ROWS * DMODEL];
__device__ float g_v[ROWS * DMODEL];
__device__ float g_attn[ROWS * DMODEL];
__device__ float g_xmid[ROWS * DMODEL];
__device__ float g_ff[ROWS * DMODEL];

// ---------------------------------------------------------------------------
// LayerNorm (torch-style: unbiased std, (x-mean)/(std+eps)*alpha + bias)
// one block per row of 1024, 256 threads, 4 elems/thread
// ---------------------------------------------------------------------------
__global__ void __launch_bounds__(256) layernorm_kernel(
    const float* __restrict__ x, const float* __restrict__ alpha,
    const float* __restrict__ beta, float* __restrict__ y) {
  __shared__ float red[8];
  __shared__ float bcast;
  const int row = blockIdx.x;
  const int tid = threadIdx.x;
  const float* xp = x + (size_t)row * DMODEL;

  float4 v = *(const float4*)(xp + tid * 4);
  float s = v.x + v.y + v.z + v.w;
#pragma unroll
  for (int o = 16; o; o >>= 1) s += __shfl_xor_sync(0xffffffffu, s, o);
  if ((tid & 31) == 0) red[tid >> 5] = s;
  __syncthreads();
  if (tid == 0) {
    float t = 0.f;
#pragma unroll
    for (int i = 0; i < 8; i++) t += red[i];
    bcast = t;
  }
  __syncthreads();
  const float mean = bcast * (1.0f / (float)DMODEL);
  __syncthreads();  // protect red/bcast reuse

  const float dx = v.x - mean, dy = v.y - mean, dz = v.z - mean, dw = v.w - mean;
  float sq = dx * dx + dy * dy + dz * dz + dw * dw;
#pragma unroll
  for (int o = 16; o; o >>= 1) sq += __shfl_xor_sync(0xffffffffu, sq, o);
  if ((tid & 31) == 0) red[tid >> 5] = sq;
  __syncthreads();
  if (tid == 0) {
    float t = 0.f;
#pragma unroll
    for (int i = 0; i < 8; i++) t += red[i];
    bcast = t;
  }
  __syncthreads();
  const float var = bcast * (1.0f / (float)(DMODEL - 1));
  const float sc = 1.0f / (sqrtf(var) + 1e-6f);

  const float4 a4 = *(const float4*)(alpha + tid * 4);
  const float4 b4 = *(const float4*)(beta + tid * 4);
  float4 o4;
  o4.x = a4.x * dx * sc + b4.x;
  o4.y = a4.y * dy * sc + b4.y;
  o4.z = a4.z * dz * sc + b4.z;
  o4.w = a4.w * dw * sc + b4.w;
  *(float4*)(y + (size_t)row * DMODEL + tid * 4) = o4;
}

// ---------------------------------------------------------------------------
// SGEMM: C[M,N] = A[M,K] @ B[K,N] (+bias) (+gelu | +residual)
// BM=128 BN=128 BK=8, 256 threads, 8x8 register tile per thread
// EPI: 0 = bias, 1 = bias+gelu, 2 = bias+residual
// ---------------------------------------------------------------------------
#define GBM 128
#define GBN 128
#define GBK 8
#define GTM 8
#define GTN 8

__device__ __forceinline__ float gelu_f(float v) {
  float t = tanhf(0.7978845608028654f * (v + 0.044715f * v * v * v));
  return 0.5f * v * (1.0f + t);
}

template <int EPI>
__global__ void __launch_bounds__(256) sgemm_kernel(
    int M, int N, int K,
    const float* __restrict__ A, const float* __restrict__ B,
    const float* __restrict__ bias, const float* __restrict__ res,
    float* __restrict__ C) {
  __shared__ float As[GBK][GBM];
  __shared__ float Bs[GBK][GBN];
  const int tid = threadIdx.x;
  const int cRow = blockIdx.y, cCol = blockIdx.x;
  const int tCol = tid & 15;   // BN/TN = 16
  const int tRow = tid >> 4;   // BM/TM = 16
  const int aRow = tid >> 1;         // 0..127
  const int aCol = (tid & 1) << 2;   // 0 or 4
  const int bRow = tid >> 5;         // 0..7
  const int bCol = (tid & 31) << 2;  // 0..124

  const float* Ap = A + (size_t)cRow * GBM * K;
  const float* Bp = B + cCol * GBN;

  float acc[GTM][GTN];
#pragma unroll
  for (int i = 0; i < GTM; i++)
#pragma unroll
    for (int j = 0; j < GTN; j++) acc[i][j] = 0.f;

  for (int k0 = 0; k0 < K; k0 += GBK) {
    float4 a4 = *(const float4*)(Ap + (size_t)aRow * K + k0 + aCol);
    As[aCol + 0][aRow] = a4.x;
    As[aCol + 1][aRow] = a4.y;
    As[aCol + 2][aRow] = a4.z;
    As[aCol + 3][aRow] = a4.w;
    *(float4*)(&Bs[bRow][bCol]) =
        *(const float4*)(Bp + (size_t)(k0 + bRow) * N + bCol);
    __syncthreads();
#pragma unroll
    for (int kk = 0; kk < GBK; kk++) {
      float regM[GTM], regN[GTN];
#pragma unroll
      for (int i = 0; i < GTM; i += 4)
        *(float4*)&regM[i] = *(const float4*)&As[kk][tRow * GTM + i];
#pragma unroll
      for (int j = 0; j < GTN; j += 4)
        *(float4*)&regN[j] = *(const float4*)&Bs[kk][tCol * GTN + j];
#pragma unroll
      for (int i = 0; i < GTM; i++)
#pragma unroll
        for (int j = 0; j < GTN; j++) acc[i][j] += regM[i] * regN[j];
    }
    __syncthreads();
  }

  const int rowBase = cRow * GBM + tRow * GTM;
  const int colBase = cCol * GBN + tCol * GTN;
  float bl[GTN];
#pragma unroll
  for (int j = 0; j < GTN; j += 4)
    *(float4*)&bl[j] = *(const float4*)(bias + colBase + j);

#pragma unroll
  for (int i = 0; i < GTM; i++) {
    float outv[GTN];
#pragma unroll
    for (int j = 0; j < GTN; j++) {
      float vv = acc[i][j] + bl[j];
      if (EPI == 1) vv = gelu_f(vv);
      outv[j] = vv;
    }
    if (EPI == 2) {
#pragma unroll
      for (int j = 0; j < GTN; j += 4) {
        float4 r4 = *(const float4*)(res + (size_t)(rowBase + i) * N + colBase + j);
        outv[j + 0] += r4.x;
        outv[j + 1] += r4.y;
        outv[j + 2] += r4.z;
        outv[j + 3] += r4.w;
      }
    }
#pragma unroll
    for (int j = 0; j < GTN; j += 4)
      *(float4*)(C + (size_t)(rowBase + i) * N + colBase + j) =
          *(float4*)&outv[j];
  }
}

// ---------------------------------------------------------------------------
// Flash attention (causal), fp32.
// Tile: 64 queries x 64 keys, DK=64. Block = 256 threads.
// thread (row = tid>>2, quad = tid&3): owns 16 scores (cols quad*16..+15)
// and 16 output dims (quad*16..+15). P exchange via warp shuffle (quad-mates
// are consecutive lanes). Qs/Ks stored transposed [d][row] for conflict-free
// broadcast reads. Static smem = exactly 48KB.
// ---------------------------------------------------------------------------
__global__ void __launch_bounds__(256) flash_attn_kernel(
    const float* __restrict__ Q, const float* __restrict__ K,
    const float* __restrict__ V, float* __restrict__ O) {
  __shared__ float Qs[64][64];  // [d][row], pre-scaled by 1/8
  __shared__ float Ks[64][64];  // [d][col]
  __shared__ float Vs[64][64];  // [k][d]

  const int qt = blockIdx.x, h = blockIdx.y, b = blockIdx.z;
  const int tid = threadIdx.x;
  const int row = tid >> 2;
  const int quad = tid & 3;
  const int lane = tid & 31;
  const int lbase = lane & ~3;
  const int q0 = qt * 64;

  // Load Q tile (transposed, scaled by 1/sqrt(DK)=0.125)
  {
    const int r = tid >> 2;
    const int d0 = (tid & 3) * 16;
    const float* qp = Q + (((size_t)(b * SEQ + q0 + r) * NHEAD + h) << 6);
#pragma unroll
    for (int j = 0; j < 16; j += 4) {
      float4 v4 = *(const float4*)(qp + d0 + j);
      Qs[d0 + j + 0][r] = v4.x * 0.125f;
      Qs[d0 + j + 1][r] = v4.y * 0.125f;
      Qs[d0 + j + 2][r] = v4.z * 0.125f;
      Qs[d0 + j + 3][r] = v4.w * 0.125f;
    }
  }

  float m = -1e30f;
  float l = 0.f;
  float Ou[16];
#pragma unroll
  for (int d = 0; d < 16; d++) Ou[d] = 0.f;

  for (int kt = 0; kt <= qt; kt++) {
    __syncthreads();
    // Load K (transposed) and V tiles
    {
      const int r = tid >> 2;
      const int d0 = (tid & 3) * 16;
      const float* kp = K + (((size_t)(b * SEQ + kt * 64 + r) * NHEAD + h) << 6);
      const float* vp = V + (((size_t)(b * SEQ + kt * 64 + r) * NHEAD + h) << 6);
#pragma unroll
      for (int j = 0; j < 16; j += 4) {
        float4 k4 = *(const float4*)(kp + d0 + j);
        Ks[d0 + j + 0][r] = k4.x;
        Ks[d0 + j + 1][r] = k4.y;
        Ks[d0 + j + 2][r] = k4.z;
        Ks[d0 + j + 3][r] = k4.w;
        *(float4*)(&Vs[r][d0 + j]) = *(const float4*)(vp + d0 + j);
      }
    }
    __syncthreads();

    // Scores: s[c] = sum_d Qs[d][row] * Ks[d][quad*16+c]  (already scaled)
    float s[16];
#pragma unroll
    for (int c = 0; c < 16; c++) s[c] = 0.f;
#pragma unroll 4
    for (int d = 0; d < 64; d++) {
      const float qv = Qs[d][row];
      const float4* kr = (const float4*)&Ks[d][quad * 16];
      float4 k0v = kr[0], k1v = kr[1], k2v = kr[2], k3v = kr[3];
      s[0] += qv * k0v.x; s[1] += qv * k0v.y; s[2] += qv * k0v.z; s[3] += qv * k0v.w;
      s[4] += qv * k1v.x; s[5] += qv * k1v.y; s[6] += qv * k1v.z; s[7] += qv * k1v.w;
      s[8] += qv * k2v.x; s[9] += qv * k2v.y; s[10] += qv * k2v.z; s[11] += qv * k2v.w;
      s[12] += qv * k3v.x; s[13] += qv * k3v.y; s[14] += qv * k3v.z; s[15] += qv * k3v.w;
    }

    // Causal mask (only diagonal tile has masked entries)
    if (kt == qt) {
#pragma unroll
      for (int c = 0; c < 16; c++)
        if (quad * 16 + c > row) s[c] = -1e9f;
    }

    // Online softmax
    float mt = s[0];
#pragma unroll
    for (int c = 1; c < 16; c++) mt = fmaxf(mt, s[c]);
    mt = fmaxf(mt, __shfl_xor_sync(0xffffffffu, mt, 1));
    mt = fmaxf(mt, __shfl_xor_sync(0xffffffffu, mt, 2));
    const float mnew = fmaxf(m, mt);
    const float corr = __expf(m - mnew);
    float lt = 0.f;
#pragma unroll
    for (int c = 0; c < 16; c++) {
      s[c] = __expf(s[c] - mnew);
      lt += s[c];
    }
    lt += __shfl_xor_sync(0xffffffffu, lt, 1);
    lt += __shfl_xor_sync(0xffffffffu, lt, 2);
    l = l * corr + lt;
    m = mnew;
#pragma unroll
    for (int d = 0; d < 16; d++) Ou[d] *= corr;

    // O += P @ V ; P broadcast via shuffle from quad-mate that owns key kk
#pragma unroll
    for (int kk = 0; kk < 64; kk++) {
      const float p = __shfl_sync(0xffffffffu, s[kk & 15], lbase + (kk >> 4));
      const float4* vr = (const float4*)&Vs[kk][quad * 16];
      float4 v0 = vr[0], v1 = vr[1], v2 = vr[2], v3 = vr[3];
      Ou[0] += p * v0.x; Ou[1] += p * v0.y; Ou[2] += p * v0.z; Ou[3] += p * v0.w;
      Ou[4] += p * v1.x; Ou[5] += p * v1.y; Ou[6] += p * v1.z; Ou[7] += p * v1.w;
      Ou[8] += p * v2.x; Ou[9] += p * v2.y; Ou[10] += p * v2.z; Ou[11] += p * v2.w;
      Ou[12] += p * v3.x; Ou[13] += p * v3.y; Ou[14] += p * v3.z; Ou[15] += p * v3.w;
    }
  }

  const float inv = 1.0f / l;
  float* op = O + (((size_t)(b * SEQ + q0 + row) * NHEAD + h) << 6) + quad * 16;
#pragma unroll
  for (int j = 0; j < 16; j += 4) {
    float4 o4;
    o4.x = Ou[j + 0] * inv;
    o4.y = Ou[j + 1] * inv;
    o4.z = Ou[j + 2] * inv;
    o4.w = Ou[j + 3] * inv;
    *(float4*)(op + j) = o4;
  }
}

// ---------------------------------------------------------------------------
// Launch
// ---------------------------------------------------------------------------
extern "C" void kernel_launch(void* const* d_in, const int* in_sizes, int n_in,
                              void* d_out, int out_size) {
  (void)in_sizes; (void)n_in; (void)out_size;
  const float* x      = (const float*)d_in[0];
  // d_in[1] = mask (int32) — causal, handled analytically
  const float* Wq     = (const float*)d_in[2];
  const float* bq     = (const float*)d_in[3];
  const float* Wk     = (const float*)d_in[4];
  const float* bk     = (const float*)d_in[5];
  const float* Wv     = (const float*)d_in[6];
  const float* bv     = (const float*)d_in[7];
  const float* Wo     = (const float*)d_in[8];
  const float* bo     = (const float*)d_in[9];
  const float* W1     = (const float*)d_in[10];
  const float* b1     = (const float*)d_in[11];
  const float* W2     = (const float*)d_in[12];
  const float* b2     = (const float*)d_in[13];
  const float* alpha1 = (const float*)d_in[14];
  const float* bias1  = (const float*)d_in[15];
  const float* alpha2 = (const float*)d_in[16];
  const float* bias2  = (const float*)d_in[17];
  float* out = (float*)d_out;

  float *x2, *q, *k, *v, *attn, *xmid, *ff;
  cudaGetSymbolAddress((void**)&x2, g_x2);
  cudaGetSymbolAddress((void**)&q, g_q);
  cudaGetSymbolAddress((void**)&k, g_k);
  cudaGetSymbolAddress((void**)&v, g_v);
  cudaGetSymbolAddress((void**)&attn, g_attn);
  cudaGetSymbolAddress((void**)&xmid, g_xmid);
  cudaGetSymbolAddress((void**)&ff, g_ff);

  const dim3 gemm_grid(DMODEL / GBN, ROWS / GBM);  // (8, 64)

  // norm1
  layernorm_kernel<<<ROWS, 256>>>(x, alpha1, bias1, x2);
  // QKV projections
  sgemm_kernel<0><<<gemm_grid, 256>>>(ROWS, DMODEL, DMODEL, x2, Wq, bq, nullptr, q);
  sgemm_kernel<0><<<gemm_grid, 256>>>(ROWS, DMODEL, DMODEL, x2, Wk, bk, nullptr, k);
  sgemm_kernel<0><<<gemm_grid, 256>>>(ROWS, DMODEL, DMODEL, x2, Wv, bv, nullptr, v);
  // causal flash attention
  flash_attn_kernel<<<dim3(SEQ / 64, NHEAD, BATCH), 256>>>(q, k, v, attn);
  // output projection + residual
  sgemm_kernel<2><<<gemm_grid, 256>>>(ROWS, DMODEL, DMODEL, attn, Wo, bo, x, xmid);
  // norm2
  layernorm_kernel<<<ROWS, 256>>>(xmid, alpha2, bias2, x2);
  // FF1 + gelu
  sgemm_kernel<1><<<gemm_grid, 256>>>(ROWS, DMODEL, DMODEL, x2, W1, b1, nullptr, ff);
  // FF2 + residual -> out
  sgemm_kernel<2><<<gemm_grid, 256>>>(ROWS, DMODEL, DMODEL, ff, W2, b2, xmid, out);
}

// round 3
// speedup vs baseline: 5.0427x; 5.0427x over previous
#include <cuda_runtime.h>
#include <math.h>

// Problem constants
#define BATCH 4
#define SEQ 2048
#define DMODEL 1024
#define NHEAD 16
#define DK 64
#define ROWS (BATCH * SEQ)   // 8192

// ---------------------------------------------------------------------------
// Scratch (device globals; no allocation allowed)
// ---------------------------------------------------------------------------
__device__ float g_x2[ROWS * DMODEL];
__device__ float g_q[ROWS * DMODEL];
__device__ float g_k[ROWS * DMODEL];
__device__ float g_v[ROWS * DMODEL];
__device__ float g_attn[ROWS * DMODEL];
__device__ float g_xmid[ROWS * DMODEL];
__device__ float g_ff[ROWS * DMODEL];

// ---------------------------------------------------------------------------
// tf32 helpers
// ---------------------------------------------------------------------------
__device__ __forceinline__ unsigned f2tf32(float f) {
  unsigned u;
  asm("cvt.rna.tf32.f32 %0, %1;" : "=r"(u) : "f"(f));
  return u;
}

__device__ __forceinline__ void mma_tf32(
    float& c0, float& c1, float& c2, float& c3,
    unsigned a0, unsigned a1, unsigned a2, unsigned a3,
    unsigned b0, unsigned b1) {
  asm("mma.sync.aligned.m16n8k8.row.col.f32.tf32.tf32.f32 "
      "{%0,%1,%2,%3}, {%4,%5,%6,%7}, {%8,%9}, {%0,%1,%2,%3};"
      : "+f"(c0), "+f"(c1), "+f"(c2), "+f"(c3)
      : "r"(a0), "r"(a1), "r"(a2), "r"(a3), "r"(b0), "r"(b1));
}

__device__ __forceinline__ float gelu_f(float v) {
  float t = tanhf(0.7978845608028654f * (v + 0.044715f * v * v * v));
  return 0.5f * v * (1.0f + t);
}

// ---------------------------------------------------------------------------
// LayerNorm (torch-style: unbiased std, (x-mean)/(std+eps)*alpha + bias)
// ---------------------------------------------------------------------------
__global__ void __launch_bounds__(256) layernorm_kernel(
    const float* __restrict__ x, const float* __restrict__ alpha,
    const float* __restrict__ beta, float* __restrict__ y) {
  __shared__ float red[8];
  __shared__ float bcast;
  const int row = blockIdx.x;
  const int tid = threadIdx.x;
  const float* xp = x + (size_t)row * DMODEL;

  float4 v = *(const float4*)(xp + tid * 4);
  float s = v.x + v.y + v.z + v.w;
#pragma unroll
  for (int o = 16; o; o >>= 1) s += __shfl_xor_sync(0xffffffffu, s, o);
  if ((tid & 31) == 0) red[tid >> 5] = s;
  __syncthreads();
  if (tid == 0) {
    float t = 0.f;
#pragma unroll
    for (int i = 0; i < 8; i++) t += red[i];
    bcast = t;
  }
  __syncthreads();
  const float mean = bcast * (1.0f / (float)DMODEL);
  __syncthreads();

  const float dx = v.x - mean, dy = v.y - mean, dz = v.z - mean, dw = v.w - mean;
  float sq = dx * dx + dy * dy + dz * dz + dw * dw;
#pragma unroll
  for (int o = 16; o; o >>= 1) sq += __shfl_xor_sync(0xffffffffu, sq, o);
  if ((tid & 31) == 0) red[tid >> 5] = sq;
  __syncthreads();
  if (tid == 0) {
    float t = 0.f;
#pragma unroll
    for (int i = 0; i < 8; i++) t += red[i];
    bcast = t;
  }
  __syncthreads();
  const float var = bcast * (1.0f / (float)(DMODEL - 1));
  const float sc = 1.0f / (sqrtf(var) + 1e-6f);

  const float4 a4 = *(const float4*)(alpha + tid * 4);
  const float4 b4 = *(const float4*)(beta + tid * 4);
  float4 o4;
  o4.x = a4.x * dx * sc + b4.x;
  o4.y = a4.y * dy * sc + b4.y;
  o4.z = a4.z * dz * sc + b4.z;
  o4.w = a4.w * dw * sc + b4.w;
  *(float4*)(y + (size_t)row * DMODEL + tid * 4) = o4;
}

// ---------------------------------------------------------------------------
// tf32 tensor-core GEMM: C[M,N] = A[M,K] @ B[K,N] (+bias)(+gelu|+residual)
// BM=128 BN=128 BK=16, 256 threads = 8 warps (2 m x 4 n), warp tile 64x32
// via m16n8k8 (4 mtiles x 4 ntiles). Double-buffered smem, tf32-converted
// at store. Padded stride 136 -> conflict-free fragment LDS.
// ---------------------------------------------------------------------------
#define TSTR 136

template <int EPI>  // 0=bias, 1=bias+gelu, 2=bias+residual
__global__ void __launch_bounds__(256) tgemm_kernel(
    int M, int N, int K,
    const float* __restrict__ A, const float* __restrict__ B,
    const float* __restrict__ bias, const float* __restrict__ res,
    float* __restrict__ C) {
  __shared__ unsigned As[2][16][TSTR];  // [k][m], tf32 bits
  __shared__ unsigned Bs[2][16][TSTR];  // [k][n], tf32 bits

  const int tid = threadIdx.x;
  const int cRow = blockIdx.y, cCol = blockIdx.x;
  const int lane = tid & 31, warp = tid >> 5;
  const int lr = lane >> 2, lc = lane & 3;
  const int m0 = (warp & 1) * 64;
  const int n0 = (warp >> 1) * 32;

  const int arow = tid >> 2;          // 0..63 (and +64)
  const int ak = (tid & 3) << 2;      // 0,4,8,12
  const int brow = tid >> 5;          // 0..7 (and +8)
  const int bn = (tid & 31) << 2;     // 0..124

  const float* Ap = A + (size_t)(cRow * 128 + arow) * K + ak;
  const float* Bp = B + (size_t)brow * N + cCol * 128 + bn;

  float acc[4][4][4];
#pragma unroll
  for (int i = 0; i < 4; i++)
#pragma unroll
    for (int j = 0; j < 4; j++)
#pragma unroll
      for (int q = 0; q < 4; q++) acc[i][j][q] = 0.f;

  // prologue: tile 0
  {
    float4 a0v = *(const float4*)(Ap);
    float4 a1v = *(const float4*)(Ap + (size_t)64 * K);
    float4 b0v = *(const float4*)(Bp);
    float4 b1v = *(const float4*)(Bp + (size_t)8 * N);
    As[0][ak + 0][arow] = f2tf32(a0v.x);
    As[0][ak + 1][arow] = f2tf32(a0v.y);
    As[0][ak + 2][arow] = f2tf32(a0v.z);
    As[0][ak + 3][arow] = f2tf32(a0v.w);
    As[0][ak + 0][arow + 64] = f2tf32(a1v.x);
    As[0][ak + 1][arow + 64] = f2tf32(a1v.y);
    As[0][ak + 2][arow + 64] = f2tf32(a1v.z);
    As[0][ak + 3][arow + 64] = f2tf32(a1v.w);
    uint4 bu0 = {f2tf32(b0v.x), f2tf32(b0v.y), f2tf32(b0v.z), f2tf32(b0v.w)};
    uint4 bu1 = {f2tf32(b1v.x), f2tf32(b1v.y), f2tf32(b1v.z), f2tf32(b1v.w)};
    *(uint4*)&Bs[0][brow][bn] = bu0;
    *(uint4*)&Bs[0][brow + 8][bn] = bu1;
  }
  __syncthreads();

  const int NT = K / 16;
  int buf = 0;
  for (int t = 0; t < NT; t++) {
    float4 a0v, a1v, b0v, b1v;
    const bool has = (t + 1 < NT);
    if (has) {
      const int k0 = (t + 1) * 16;
      a0v = *(const float4*)(Ap + k0);
      a1v = *(const float4*)(Ap + (size_t)64 * K + k0);
      b0v = *(const float4*)(Bp + (size_t)k0 * N);
      b1v = *(const float4*)(Bp + (size_t)(k0 + 8) * N);
    }

#pragma unroll
    for (int ks = 0; ks < 2; ks++) {
      const int kb = ks * 8;
      unsigned af[4][4], bf[4][2];
#pragma unroll
      for (int mt = 0; mt < 4; mt++) {
        const int m = m0 + mt * 16 + lr;
        af[mt][0] = As[buf][kb + lc][m];
        af[mt][1] = As[buf][kb + lc][m + 8];
        af[mt][2] = As[buf][kb + 4 + lc][m];
        af[mt][3] = As[buf][kb + 4 + lc][m + 8];
      }
#pragma unroll
      for (int nt = 0; nt < 4; nt++) {
        const int n = n0 + nt * 8 + lr;
        bf[nt][0] = Bs[buf][kb + lc][n];
        bf[nt][1] = Bs[buf][kb + 4 + lc][n];
      }
#pragma unroll
      for (int mt = 0; mt < 4; mt++)
#pragma unroll
        for (int nt = 0; nt < 4; nt++)
          mma_tf32(acc[mt][nt][0], acc[mt][nt][1], acc[mt][nt][2], acc[mt][nt][3],
                   af[mt][0], af[mt][1], af[mt][2], af[mt][3],
                   bf[nt][0], bf[nt][1]);
    }

    if (has) {
      const int nb = buf ^ 1;
      As[nb][ak + 0][arow] = f2tf32(a0v.x);
      As[nb][ak + 1][arow] = f2tf32(a0v.y);
      As[nb][ak + 2][arow] = f2tf32(a0v.z);
      As[nb][ak + 3][arow] = f2tf32(a0v.w);
      As[nb][ak + 0][arow + 64] = f2tf32(a1v.x);
      As[nb][ak + 1][arow + 64] = f2tf32(a1v.y);
      As[nb][ak + 2][arow + 64] = f2tf32(a1v.z);
      As[nb][ak + 3][arow + 64] = f2tf32(a1v.w);
      uint4 bu0 = {f2tf32(b0v.x), f2tf32(b0v.y), f2tf32(b0v.z), f2tf32(b0v.w)};
      uint4 bu1 = {f2tf32(b1v.x), f2tf32(b1v.y), f2tf32(b1v.z), f2tf32(b1v.w)};
      *(uint4*)&Bs[nb][brow][bn] = bu0;
      *(uint4*)&Bs[nb][brow + 8][bn] = bu1;
      __syncthreads();
      buf = nb;
    }
  }

  // epilogue
#pragma unroll
  for (int mt = 0; mt < 4; mt++) {
    const int r0 = cRow * 128 + m0 + mt * 16 + lr;
#pragma unroll
    for (int nt = 0; nt < 4; nt++) {
      const int col = cCol * 128 + n0 + nt * 8 + 2 * lc;
      const float bx = bias[col], by = bias[col + 1];
      float v0 = acc[mt][nt][0] + bx, v1 = acc[mt][nt][1] + by;
      float v2 = acc[mt][nt][2] + bx, v3 = acc[mt][nt][3] + by;
      if (EPI == 1) { v0 = gelu_f(v0); v1 = gelu_f(v1); v2 = gelu_f(v2); v3 = gelu_f(v3); }
      if (EPI == 2) {
        const float2 r4a = *(const float2*)(res + (size_t)r0 * N + col);
        const float2 r4b = *(const float2*)(res + (size_t)(r0 + 8) * N + col);
        v0 += r4a.x; v1 += r4a.y; v2 += r4b.x; v3 += r4b.y;
      }
      float2 o0 = {v0, v1}, o1 = {v2, v3};
      *(float2*)(C + (size_t)r0 * N + col) = o0;
      *(float2*)(C + (size_t)(r0 + 8) * N + col) = o1;
    }
  }
}

// ---------------------------------------------------------------------------
// Flash attention (causal) with tf32 tensor cores.
// Block: 256 threads = 8 warps, tile 64 q x 64 k, DK=64.
// Warp w: S/O rows 16*(w>>1), cols 32*(w&1); m16n8k8 (1 mtile x 4 ntiles).
// Q fragments preloaded to registers. S -> smem -> softmax -> P (tf32,
// in place) -> PV mma. Smem strides 68 (Q/S/K) and 72 (V): conflict-free
// fragment loads. Dynamic smem = 53760 B.
// ---------------------------------------------------------------------------
#define ATTN_SMEM (2 * 64 * 68 * 4 + 64 * 72 * 4 + 2 * 64 * 4)

__global__ void __launch_bounds__(256) flash_attn_tc_kernel(
    const float* __restrict__ Q, const float* __restrict__ K,
    const float* __restrict__ V, float* __restrict__ O) {
  extern __shared__ char smem[];
  float* Sf = (float*)smem;                         // [64][68]: Q stage, S, P
  unsigned* Su = (unsigned*)smem;
  unsigned* Ks = (unsigned*)(smem + 64 * 68 * 4);   // [64][68] tf32
  unsigned* Vs = (unsigned*)(smem + 2 * 64 * 68 * 4);  // [64][72] tf32
  float* corr_s = (float*)(smem + 2 * 64 * 68 * 4 + 64 * 72 * 4);  // [64]
  float* l_s = corr_s + 64;                         // [64]

  const int qt = blockIdx.x, h = blockIdx.y, b = blockIdx.z;
  const int tid = threadIdx.x;
  const int lane = tid & 31, warp = tid >> 5;
  const int lr = lane >> 2, lc = lane & 3;
  const int mq = (warp >> 1) * 16;  // S/O row base
  const int nq = (warp & 1) * 32;   // S col base (also O col base)
  const int q0 = qt * 64;

  // ---- Load + scale Q into Sf, then extract fragments to registers ----
#pragma unroll
  for (int i = 0; i < 4; i++) {
    const int idx = tid + i * 256;
    const int r = idx >> 4, d0 = (idx & 15) << 2;
    float4 v4 = *(const float4*)(
        Q + (((size_t)((b * SEQ + q0 + r) * NHEAD + h)) << 6) + d0);
    v4.x *= 0.125f; v4.y *= 0.125f; v4.z *= 0.125f; v4.w *= 0.125f;
    *(float4*)(Sf + r * 68 + d0) = v4;
  }
  __syncthreads();
  unsigned qa[8][4];
#pragma unroll
  for (int ks = 0; ks < 8; ks++) {
    const int c = ks * 8 + lc;
    qa[ks][0] = f2tf32(Sf[(mq + lr) * 68 + c]);
    qa[ks][1] = f2tf32(Sf[(mq + 8 + lr) * 68 + c]);
    qa[ks][2] = f2tf32(Sf[(mq + lr) * 68 + c + 4]);
    qa[ks][3] = f2tf32(Sf[(mq + 8 + lr) * 68 + c + 4]);
  }

  float oacc[4][4];
#pragma unroll
  for (int nt = 0; nt < 4; nt++)
#pragma unroll
    for (int q = 0; q < 4; q++) oacc[nt][q] = 0.f;

  // softmax-owner role: thread owns row srow (4 threads per row, redundant)
  const int srow = tid >> 2, sseg = tid & 3;
  float mrow = -1e30f, lrow = 0.f;

  for (int kt = 0; kt <= qt; kt++) {
    __syncthreads();  // prev PV reads of Ps/Vs/Ks done; Q frags extracted
    // ---- Load K, V tiles (tf32-converted) ----
#pragma unroll
    for (int i = 0; i < 4; i++) {
      const int idx = tid + i * 256;
      const int r = idx >> 4, d0 = (idx & 15) << 2;
      const size_t g =
          (((size_t)((b * SEQ + kt * 64 + r) * NHEAD + h)) << 6) + d0;
      const float4 kk = *(const float4*)(K + g);
      const float4 vv = *(const float4*)(V + g);
      uint4 ku = {f2tf32(kk.x), f2tf32(kk.y), f2tf32(kk.z), f2tf32(kk.w)};
      uint4 vu = {f2tf32(vv.x), f2tf32(vv.y), f2tf32(vv.z), f2tf32(vv.w)};
      *(uint4*)(Ks + r * 68 + d0) = ku;
      *(uint4*)(Vs + r * 72 + d0) = vu;
    }
    __syncthreads();

    // ---- S = Q @ K^T (scaled) ----
    float sacc[4][4];
#pragma unroll
    for (int nt = 0; nt < 4; nt++)
#pragma unroll
      for (int q = 0; q < 4; q++) sacc[nt][q] = 0.f;
#pragma unroll
    for (int ks = 0; ks < 8; ks++) {
      const int kb = ks * 8;
#pragma unroll
      for (int nt = 0; nt < 4; nt++) {
        const int key = nq + nt * 8 + lr;
        const unsigned b0 = Ks[key * 68 + kb + lc];
        const unsigned b1 = Ks[key * 68 + kb + 4 + lc];
        mma_tf32(sacc[nt][0], sacc[nt][1], sacc[nt][2], sacc[nt][3],
                 qa[ks][0], qa[ks][1], qa[ks][2], qa[ks][3], b0, b1);
      }
    }
    // write S to smem
#pragma unroll
    for (int nt = 0; nt < 4; nt++) {
      const int col = nq + nt * 8 + 2 * lc;
      float2 s01 = {sacc[nt][0], sacc[nt][1]};
      float2 s23 = {sacc[nt][2], sacc[nt][3]};
      *(float2*)(Sf + (mq + lr) * 68 + col) = s01;
      *(float2*)(Sf + (mq + 8 + lr) * 68 + col) = s23;
    }
    __syncthreads();

    // ---- online softmax: thread handles 16 cols of row srow ----
    float sv[16];
    {
      const float4* sp = (const float4*)(Sf + srow * 68 + sseg * 16);
      ((float4*)sv)[0] = sp[0];
      ((float4*)sv)[1] = sp[1];
      ((float4*)sv)[2] = sp[2];
      ((float4*)sv)[3] = sp[3];
    }
    if (kt == qt) {
#pragma unroll
      for (int j = 0; j < 16; j++)
        if (sseg * 16 + j > srow) sv[j] = -1e9f;
    }
    float mt = sv[0];
#pragma unroll
    for (int j = 1; j < 16; j++) mt = fmaxf(mt, sv[j]);
    mt = fmaxf(mt, __shfl_xor_sync(0xffffffffu, mt, 1));
    mt = fmaxf(mt, __shfl_xor_sync(0xffffffffu, mt, 2));
    const float mnew = fmaxf(mrow, mt);
    const float corr = __expf(mrow - mnew);
    float sum = 0.f;
#pragma unroll
    for (int j = 0; j < 16; j++) {
      sv[j] = __expf(sv[j] - mnew);
      sum += sv[j];
    }
    sum += __shfl_xor_sync(0xffffffffu, sum, 1);
    sum += __shfl_xor_sync(0xffffffffu, sum, 2);
    lrow = lrow * corr + sum;
    mrow = mnew;
    // write P (tf32) in place
    {
      unsigned* pd = Su + srow * 68 + sseg * 16;
#pragma unroll
      for (int qy = 0; qy < 4; qy++) {
        uint4 u = {f2tf32(sv[4 * qy + 0]), f2tf32(sv[4 * qy + 1]),
                   f2tf32(sv[4 * qy + 2]), f2tf32(sv[4 * qy + 3])};
        *(uint4*)(pd + 4 * qy) = u;
      }
    }
    if (sseg == 0) { corr_s[srow] = corr; l_s[srow] = lrow; }
    __syncthreads();

    // ---- rescale O, then O += P @ V ----
    const float cr0 = corr_s[mq + lr];
    const float cr1 = corr_s[mq + 8 + lr];
#pragma unroll
    for (int nt = 0; nt < 4; nt++) {
      oacc[nt][0] *= cr0; oacc[nt][1] *= cr0;
      oacc[nt][2] *= cr1; oacc[nt][3] *= cr1;
    }
#pragma unroll
    for (int ks = 0; ks < 8; ks++) {
      const int kb = ks * 8;
      const unsigned pa0 = Su[(mq + lr) * 68 + kb + lc];
      const unsigned pa1 = Su[(mq + 8 + lr) * 68 + kb + lc];
      const unsigned pa2 = Su[(mq + lr) * 68 + kb + 4 + lc];
      const unsigned pa3 = Su[(mq + 8 + lr) * 68 + kb + 4 + lc];
#pragma unroll
      for (int nt = 0; nt < 4; nt++) {
        const int d = nq + nt * 8 + lr;
        const unsigned b0 = Vs[(kb + lc) * 72 + d];
        const unsigned b1 = Vs[(kb + 4 + lc) * 72 + d];
        mma_tf32(oacc[nt][0], oacc[nt][1], oacc[nt][2], oacc[nt][3],
                 pa0, pa1, pa2, pa3, b0, b1);
      }
    }
  }

  // ---- finalize: O /= l, write to gmem ([b,s,h,d] layout) ----
  const float inv0 = 1.0f / l_s[mq + lr];
  const float inv1 = 1.0f / l_s[mq + 8 + lr];
#pragma unroll
  for (int nt = 0; nt < 4; nt++) {
    const int col = nq + nt * 8 + 2 * lc;
    float* o0 = O + (((size_t)((b * SEQ + q0 + mq + lr) * NHEAD + h)) << 6) + col;
    float* o1 = O + (((size_t)((b * SEQ + q0 + mq + 8 + lr) * NHEAD + h)) << 6) + col;
    float2 w0 = {oacc[nt][0] * inv0, oacc[nt][1] * inv0};
    float2 w1 = {oacc[nt][2] * inv1, oacc[nt][3] * inv1};
    *(float2*)o0 = w0;
    *(float2*)o1 = w1;
  }
}

// ---------------------------------------------------------------------------
// Launch
// ---------------------------------------------------------------------------
extern "C" void kernel_launch(void* const* d_in, const int* in_sizes, int n_in,
                              void* d_out, int out_size) {
  (void)in_sizes; (void)n_in; (void)out_size;
  const float* x      = (const float*)d_in[0];
  // d_in[1] = mask (int32) — causal, handled analytically
  const float* Wq     = (const float*)d_in[2];
  const float* bq     = (const float*)d_in[3];
  const float* Wk     = (const float*)d_in[4];
  const float* bk     = (const float*)d_in[5];
  const float* Wv     = (const float*)d_in[6];
  const float* bv     = (const float*)d_in[7];
  const float* Wo     = (const float*)d_in[8];
  const float* bo     = (const float*)d_in[9];
  const float* W1     = (const float*)d_in[10];
  const float* b1     = (const float*)d_in[11];
  const float* W2     = (const float*)d_in[12];
  const float* b2     = (const float*)d_in[13];
  const float* alpha1 = (const float*)d_in[14];
  const float* bias1  = (const float*)d_in[15];
  const float* alpha2 = (const float*)d_in[16];
  const float* bias2  = (const float*)d_in[17];
  float* out = (float*)d_out;

  float *x2, *q, *k, *v, *attn, *xmid, *ff;
  cudaGetSymbolAddress((void**)&x2, g_x2);
  cudaGetSymbolAddress((void**)&q, g_q);
  cudaGetSymbolAddress((void**)&k, g_k);
  cudaGetSymbolAddress((void**)&v, g_v);
  cudaGetSymbolAddress((void**)&attn, g_attn);
  cudaGetSymbolAddress((void**)&xmid, g_xmid);
  cudaGetSymbolAddress((void**)&ff, g_ff);

  static int attn_smem_set = 0;
  if (!attn_smem_set) {
    cudaFuncSetAttribute(flash_attn_tc_kernel,
                         cudaFuncAttributeMaxDynamicSharedMemorySize, ATTN_SMEM);
    attn_smem_set = 1;
  }

  const dim3 gemm_grid(DMODEL / 128, ROWS / 128);  // (8, 64)

  layernorm_kernel<<<ROWS, 256>>>(x, alpha1, bias1, x2);
  tgemm_kernel<0><<<gemm_grid, 256>>>(ROWS, DMODEL, DMODEL, x2, Wq, bq, nullptr, q);
  tgemm_kernel<0><<<gemm_grid, 256>>>(ROWS, DMODEL, DMODEL, x2, Wk, bk, nullptr, k);
  tgemm_kernel<0><<<gemm_grid, 256>>>(ROWS, DMODEL, DMODEL, x2, Wv, bv, nullptr, v);
  flash_attn_tc_kernel<<<dim3(SEQ / 64, NHEAD, BATCH), 256, ATTN_SMEM>>>(q, k, v, attn);
  tgemm_kernel<2><<<gemm_grid, 256>>>(ROWS, DMODEL, DMODEL, attn, Wo, bo, x, xmid);
  layernorm_kernel<<<ROWS, 256>>>(xmid, alpha2, bias2, x2);
  tgemm_kernel<1><<<gemm_grid, 256>>>(ROWS, DMODEL, DMODEL, x2, W1, b1, nullptr, ff);
  tgemm_kernel<2><<<gemm_grid, 256>>>(ROWS, DMODEL, DMODEL, ff, W2, b2, xmid, out);
}

// round 4
// speedup vs baseline: 5.1861x; 1.0284x over previous
#include <cuda_runtime.h>
#include <math.h>

// Problem constants
#define BATCH 4
#define SEQ 2048
#define DMODEL 1024
#define NHEAD 16
#define DK 64
#define ROWS (BATCH * SEQ)   // 8192

// ---------------------------------------------------------------------------
// Scratch (device globals; no allocation allowed)
// ---------------------------------------------------------------------------
__device__ float g_x2[ROWS * DMODEL];
__device__ float g_q[ROWS * DMODEL];
__device__ float g_k[ROWS * DMODEL];
__device__ float g_v[ROWS * DMODEL];
__device__ float g_attn[ROWS * DMODEL];
__device__ float g_xmid[ROWS * DMODEL];
__device__ float g_ff[ROWS * DMODEL];

// ---------------------------------------------------------------------------
// tf32 helpers
// ---------------------------------------------------------------------------
__device__ __forceinline__ unsigned f2tf32(float f) {
  unsigned u;
  asm("cvt.rna.tf32.f32 %0, %1;" : "=r"(u) : "f"(f));
  return u;
}

__device__ __forceinline__ void mma_tf32(
    float& c0, float& c1, float& c2, float& c3,
    unsigned a0, unsigned a1, unsigned a2, unsigned a3,
    unsigned b0, unsigned b1) {
  asm("mma.sync.aligned.m16n8k8.row.col.f32.tf32.tf32.f32 "
      "{%0,%1,%2,%3}, {%4,%5,%6,%7}, {%8,%9}, {%0,%1,%2,%3};"
      : "+f"(c0), "+f"(c1), "+f"(c2), "+f"(c3)
      : "r"(a0), "r"(a1), "r"(a2), "r"(a3), "r"(b0), "r"(b1));
}

__device__ __forceinline__ float gelu_f(float v) {
  float t = tanhf(0.7978845608028654f * (v + 0.044715f * v * v * v));
  return 0.5f * v * (1.0f + t);
}

// ---------------------------------------------------------------------------
// LayerNorm
// ---------------------------------------------------------------------------
__global__ void __launch_bounds__(256) layernorm_kernel(
    const float* __restrict__ x, const float* __restrict__ alpha,
    const float* __restrict__ beta, float* __restrict__ y) {
  __shared__ float red[8];
  __shared__ float bcast;
  const int row = blockIdx.x;
  const int tid = threadIdx.x;
  const float* xp = x + (size_t)row * DMODEL;

  float4 v = *(const float4*)(xp + tid * 4);
  float s = v.x + v.y + v.z + v.w;
#pragma unroll
  for (int o = 16; o; o >>= 1) s += __shfl_xor_sync(0xffffffffu, s, o);
  if ((tid & 31) == 0) red[tid >> 5] = s;
  __syncthreads();
  if (tid == 0) {
    float t = 0.f;
#pragma unroll
    for (int i = 0; i < 8; i++) t += red[i];
    bcast = t;
  }
  __syncthreads();
  const float mean = bcast * (1.0f / (float)DMODEL);
  __syncthreads();

  const float dx = v.x - mean, dy = v.y - mean, dz = v.z - mean, dw = v.w - mean;
  float sq = dx * dx + dy * dy + dz * dz + dw * dw;
#pragma unroll
  for (int o = 16; o; o >>= 1) sq += __shfl_xor_sync(0xffffffffu, sq, o);
  if ((tid & 31) == 0) red[tid >> 5] = sq;
  __syncthreads();
  if (tid == 0) {
    float t = 0.f;
#pragma unroll
    for (int i = 0; i < 8; i++) t += red[i];
    bcast = t;
  }
  __syncthreads();
  const float var = bcast * (1.0f / (float)(DMODEL - 1));
  const float sc = 1.0f / (sqrtf(var) + 1e-6f);

  const float4 a4 = *(const float4*)(alpha + tid * 4);
  const float4 b4 = *(const float4*)(beta + tid * 4);
  float4 o4;
  o4.x = a4.x * dx * sc + b4.x;
  o4.y = a4.y * dy * sc + b4.y;
  o4.z = a4.z * dz * sc + b4.z;
  o4.w = a4.w * dw * sc + b4.w;
  *(float4*)(y + (size_t)row * DMODEL + tid * 4) = o4;
}

// ---------------------------------------------------------------------------
// tf32 TC GEMM with fragment-packed smem.
// BM=128 BN=128 BK=16, 256 thr = 8 warps (2m x 4n), warp tile 64x32.
// A frags: [buf][ks][mtile(8)][32 lanes x uint4]  (LDS.128, swizzled)
// B frags: [buf][ks][ntile(16)][68-word tile: 32 lanes x uint2 + pad]
// ---------------------------------------------------------------------------
// A store: element(m, k=ak+j) -> tile ((buf*2+ks)*8+mt)*128, word (lane^s)*4+q
__device__ __forceinline__ void store_A_frag(unsigned* Asm, int buf, int m,
                                             int ak, float4 a) {
  const int ks = ak >> 3;
  const int khi = (ak >> 2) & 1;
  const int mt = m >> 4;
  const int r = m & 15;
  const int lr = r & 7;
  const int q = (r >> 3) + 2 * khi;
  const int s = (lr >> 1) & 3;  // = (lane>>3)&3 since lane = lr*4+lc
  unsigned* base = Asm + (((buf * 2 + ks) * 8 + mt) << 7) + q;
  const int l0 = lr * 4;
  base[(l0 + (0 ^ s)) * 4] = f2tf32(a.x);
  base[(l0 + (1 ^ s)) * 4] = f2tf32(a.y);
  base[(l0 + (2 ^ s)) * 4] = f2tf32(a.z);
  base[(l0 + (3 ^ s)) * 4] = f2tf32(a.w);
}

// B store: element(k, n=bn+j) -> tile ((buf*2+ks)*16+nt)*68, word piB(lane)*2+p
__device__ __forceinline__ void store_B_frag(unsigned* Bsm, int buf, int k,
                                             int bn, float4 b) {
  const int ks = k >> 3;
  const int kc = k & 7;
  const int lc = kc & 3;
  const int p = kc >> 2;
  const int nt = bn >> 3;
  const int lr0 = bn & 7;  // 0 or 4 (bn is multiple of 4)
  unsigned* base = Bsm + ((buf * 2 + ks) * 16 + nt) * 68 + p;
  const float w[4] = {b.x, b.y, b.z, b.w};
#pragma unroll
  for (int j = 0; j < 4; j++) {
    const int lane = (lr0 + j) * 4 + lc;
    const int pl = lane ^ (((lane >> 4) & 1) << 1);
    base[pl * 2] = f2tf32(w[j]);
  }
}

template <int EPI>  // 0=bias, 1=bias+gelu, 2=bias+residual
__device__ __forceinline__ void gemm_body(
    int N, int K,
    const float* __restrict__ A, const float* __restrict__ B,
    const float* __restrict__ bias, const float* __restrict__ res,
    float* __restrict__ C) {
  __shared__ unsigned Asm[2 * 2 * 8 * 128];   // 16 KB
  __shared__ unsigned Bsm[2 * 2 * 16 * 68];   // 17 KB

  const int tid = threadIdx.x;
  const int cRow = blockIdx.y, cCol = blockIdx.x;
  const int lane = tid & 31, warp = tid >> 5;
  const int lr = lane >> 2, lc = lane & 3;
  const int m0 = (warp & 1) * 64;
  const int n0 = (warp >> 1) * 32;
  const int la = (lane ^ ((lane >> 3) & 3)) * 4;                // A consumer swizzle
  const int lb = (lane ^ (((lane >> 4) & 1) << 1)) * 2;        // B consumer swizzle

  const int arow = tid >> 2;          // 0..63 (and +64)
  const int ak = (tid & 3) << 2;      // 0,4,8,12
  const int brow = tid >> 5;          // 0..7 (and +8)
  const int bn = (tid & 31) << 2;     // 0..124

  const float* Ap = A + (size_t)(cRow * 128 + arow) * K + ak;
  const float* Bp = B + (size_t)brow * N + cCol * 128 + bn;

  float acc[4][4][4];
#pragma unroll
  for (int i = 0; i < 4; i++)
#pragma unroll
    for (int j = 0; j < 4; j++)
#pragma unroll
      for (int q = 0; q < 4; q++) acc[i][j][q] = 0.f;

  // prologue: tile 0
  {
    float4 a0v = *(const float4*)(Ap);
    float4 a1v = *(const float4*)(Ap + (size_t)64 * K);
    float4 b0v = *(const float4*)(Bp);
    float4 b1v = *(const float4*)(Bp + (size_t)8 * N);
    store_A_frag(Asm, 0, arow, ak, a0v);
    store_A_frag(Asm, 0, arow + 64, ak, a1v);
    store_B_frag(Bsm, 0, brow, bn, b0v);
    store_B_frag(Bsm, 0, brow + 8, bn, b1v);
  }
  __syncthreads();

  const int NT = K / 16;
  int buf = 0;
  for (int t = 0; t < NT; t++) {
    float4 a0v, a1v, b0v, b1v;
    const bool has = (t + 1 < NT);
    if (has) {
      const int k0 = (t + 1) * 16;
      a0v = *(const float4*)(Ap + k0);
      a1v = *(const float4*)(Ap + (size_t)64 * K + k0);
      b0v = *(const float4*)(Bp + (size_t)k0 * N);
      b1v = *(const float4*)(Bp + (size_t)(k0 + 8) * N);
    }

#pragma unroll
    for (int ks = 0; ks < 2; ks++) {
      const unsigned* Ab = Asm + (((buf * 2 + ks) * 8 + (m0 >> 4)) << 7);
      const unsigned* Bb = Bsm + ((buf * 2 + ks) * 16 + (n0 >> 3)) * 68;
      uint4 af[4];
      uint2 bf[4];
#pragma unroll
      for (int mt = 0; mt < 4; mt++)
        af[mt] = *(const uint4*)(Ab + (mt << 7) + la);
#pragma unroll
      for (int nt = 0; nt < 4; nt++)
        bf[nt] = *(const uint2*)(Bb + nt * 68 + lb);
#pragma unroll
      for (int mt = 0; mt < 4; mt++)
#pragma unroll
        for (int nt = 0; nt < 4; nt++)
          mma_tf32(acc[mt][nt][0], acc[mt][nt][1], acc[mt][nt][2], acc[mt][nt][3],
                   af[mt].x, af[mt].y, af[mt].z, af[mt].w,
                   bf[nt].x, bf[nt].y);
    }

    if (has) {
      const int nb = buf ^ 1;
      store_A_frag(Asm, nb, arow, ak, a0v);
      store_A_frag(Asm, nb, arow + 64, ak, a1v);
      store_B_frag(Bsm, nb, brow, bn, b0v);
      store_B_frag(Bsm, nb, brow + 8, bn, b1v);
      __syncthreads();
      buf = nb;
    }
  }

  // epilogue
#pragma unroll
  for (int mt = 0; mt < 4; mt++) {
    const int r0 = cRow * 128 + m0 + mt * 16 + lr;
#pragma unroll
    for (int nt = 0; nt < 4; nt++) {
      const int col = cCol * 128 + n0 + nt * 8 + 2 * lc;
      const float bx = bias[col], by = bias[col + 1];
      float v0 = acc[mt][nt][0] + bx, v1 = acc[mt][nt][1] + by;
      float v2 = acc[mt][nt][2] + bx, v3 = acc[mt][nt][3] + by;
      if (EPI == 1) { v0 = gelu_f(v0); v1 = gelu_f(v1); v2 = gelu_f(v2); v3 = gelu_f(v3); }
      if (EPI == 2) {
        const float2 r4a = *(const float2*)(res + (size_t)r0 * N + col);
        const float2 r4b = *(const float2*)(res + (size_t)(r0 + 8) * N + col);
        v0 += r4a.x; v1 += r4a.y; v2 += r4b.x; v3 += r4b.y;
      }
      float2 o0 = {v0, v1}, o1 = {v2, v3};
      *(float2*)(C + (size_t)r0 * N + col) = o0;
      *(float2*)(C + (size_t)(r0 + 8) * N + col) = o1;
    }
  }
}

template <int EPI>
__global__ void __launch_bounds__(256) tgemm_kernel(
    int N, int K,
    const float* __restrict__ A, const float* __restrict__ B,
    const float* __restrict__ bias, const float* __restrict__ res,
    float* __restrict__ C) {
  gemm_body<EPI>(N, K, A, B, bias, res, C);
}

// Fused QKV: grid.z selects which projection
__global__ void __launch_bounds__(256) qkv_kernel(
    int N, int K, const float* __restrict__ A,
    const float* __restrict__ Wq, const float* __restrict__ bq, float* __restrict__ q,
    const float* __restrict__ Wk, const float* __restrict__ bk, float* __restrict__ k,
    const float* __restrict__ Wv, const float* __restrict__ bv, float* __restrict__ v) {
  const float* B;
  const float* bias;
  float* C;
  if (blockIdx.z == 0)      { B = Wq; bias = bq; C = q; }
  else if (blockIdx.z == 1) { B = Wk; bias = bk; C = k; }
  else                      { B = Wv; bias = bv; C = v; }
  gemm_body<0>(N, K, A, B, bias, nullptr, C);
}

// ---------------------------------------------------------------------------
// Flash attention (causal), tf32 TC, fragment-packed K/V smem.
// 256 thr = 8 warps, tile 64q x 64k, DK=64.
// Sf: [64][68] f32 (Q stage / S / P).  Kf,Vf: [ks(8)][nt(8)][68w] packed frags.
// ---------------------------------------------------------------------------
#define SF_BYTES (64 * 68 * 4)          // 17408
#define KF_BYTES (8 * 8 * 68 * 4)       // 17408
#define ATTN_SMEM (SF_BYTES + 2 * KF_BYTES + 512)

__global__ void __launch_bounds__(256) flash_attn_tc_kernel(
    const float* __restrict__ Q, const float* __restrict__ K,
    const float* __restrict__ V, float* __restrict__ O) {
  extern __shared__ char smem[];
  float* Sf = (float*)smem;
  unsigned* Su = (unsigned*)smem;
  unsigned* Kf = (unsigned*)(smem + SF_BYTES);
  unsigned* Vf = (unsigned*)(smem + SF_BYTES + KF_BYTES);
  float* corr_s = (float*)(smem + SF_BYTES + 2 * KF_BYTES);
  float* l_s = corr_s + 64;

  const int qt = blockIdx.x, h = blockIdx.y, b = blockIdx.z;
  const int tid = threadIdx.x;
  const int lane = tid & 31, warp = tid >> 5;
  const int lr = lane >> 2, lc = lane & 3;
  const int mq = (warp >> 1) * 16;
  const int nq = (warp & 1) * 32;
  const int q0 = qt * 64;

  // ---- Load + scale Q into Sf, extract fragments to registers ----
#pragma unroll
  for (int i = 0; i < 4; i++) {
    const int idx = tid + i * 256;
    const int r = idx >> 4, d0 = (idx & 15) << 2;
    float4 v4 = *(const float4*)(
        Q + (((size_t)((b * SEQ + q0 + r) * NHEAD + h)) << 6) + d0);
    v4.x *= 0.125f; v4.y *= 0.125f; v4.z *= 0.125f; v4.w *= 0.125f;
    *(float4*)(Sf + r * 68 + d0) = v4;
  }
  __syncthreads();
  unsigned qa[8][4];
#pragma unroll
  for (int ks = 0; ks < 8; ks++) {
    const int c = ks * 8 + lc;
    qa[ks][0] = f2tf32(Sf[(mq + lr) * 68 + c]);
    qa[ks][1] = f2tf32(Sf[(mq + 8 + lr) * 68 + c]);
    qa[ks][2] = f2tf32(Sf[(mq + lr) * 68 + c + 4]);
    qa[ks][3] = f2tf32(Sf[(mq + 8 + lr) * 68 + c + 4]);
  }

  float oacc[4][4];
#pragma unroll
  for (int nt = 0; nt < 4; nt++)
#pragma unroll
    for (int q = 0; q < 4; q++) oacc[nt][q] = 0.f;

  const int srow = tid >> 2, sseg = tid & 3;
  float mrow = -1e30f, lrow = 0.f;

  for (int kt = 0; kt <= qt; kt++) {
    __syncthreads();
    // ---- Load K,V -> packed fragment smem ----
#pragma unroll
    for (int i = 0; i < 4; i++) {
      const int idx = tid + i * 256;
      const int r = idx >> 4, d0 = (idx & 15) << 2;
      const size_t g =
          (((size_t)((b * SEQ + kt * 64 + r) * NHEAD + h)) << 6) + d0;
      const float4 kk = *(const float4*)(K + g);
      const float4 vv = *(const float4*)(V + g);
      // K as B-frag of S-mma: k-index = d, n-index = key(=r)
      {
        const int ksb = d0 >> 3;
        const int p = (d0 >> 2) & 1;
        const int nt = r >> 3, lrk = r & 7;
        unsigned* base = Kf + ((ksb * 8 + nt) * 68) + p;
        const int sx = ksb & 3;
        const int l0 = lrk * 4;
        const float w[4] = {kk.x, kk.y, kk.z, kk.w};
#pragma unroll
        for (int j = 0; j < 4; j++)
          base[(l0 + (j ^ sx)) * 2] = f2tf32(w[j]);
      }
      // V as B-frag of PV-mma: k-index = key(=r), n-index = d
      {
        const int ksv = r >> 3;
        const int kc = r & 7;
        const int lcv = kc & 3, p = kc >> 2;
        const int nt = d0 >> 3, lr0 = d0 & 7;  // lr0 in {0,4}
        unsigned* base = Vf + ((ksv * 8 + nt) * 68) + p;
        const float w[4] = {vv.x, vv.y, vv.z, vv.w};
#pragma unroll
        for (int j = 0; j < 4; j++)
          base[((lr0 + j) * 4 + lcv) * 2] = f2tf32(w[j]);
      }
    }
    __syncthreads();

    // ---- S = Q @ K^T ----
    float sacc[4][4];
#pragma unroll
    for (int nt = 0; nt < 4; nt++)
#pragma unroll
      for (int q = 0; q < 4; q++) sacc[nt][q] = 0.f;
#pragma unroll
    for (int ks = 0; ks < 8; ks++) {
      const unsigned* Kb = Kf + (ks * 8 + (nq >> 3)) * 68 + (lane ^ (ks & 3)) * 2;
#pragma unroll
      for (int nt = 0; nt < 4; nt++) {
        const uint2 kb2 = *(const uint2*)(Kb + nt * 68);
        mma_tf32(sacc[nt][0], sacc[nt][1], sacc[nt][2], sacc[nt][3],
                 qa[ks][0], qa[ks][1], qa[ks][2], qa[ks][3], kb2.x, kb2.y);
      }
    }
    // write S to smem
#pragma unroll
    for (int nt = 0; nt < 4; nt++) {
      const int col = nq + nt * 8 + 2 * lc;
      float2 s01 = {sacc[nt][0], sacc[nt][1]};
      float2 s23 = {sacc[nt][2], sacc[nt][3]};
      *(float2*)(Sf + (mq + lr) * 68 + col) = s01;
      *(float2*)(Sf + (mq + 8 + lr) * 68 + col) = s23;
    }
    __syncthreads();

    // ---- online softmax (thread: row srow, cols sseg*16..+15) ----
    float sv[16];
    {
      const float4* sp = (const float4*)(Sf + srow * 68 + sseg * 16);
      ((float4*)sv)[0] = sp[0];
      ((float4*)sv)[1] = sp[1];
      ((float4*)sv)[2] = sp[2];
      ((float4*)sv)[3] = sp[3];
    }
    if (kt == qt) {
#pragma unroll
      for (int j = 0; j < 16; j++)
        if (sseg * 16 + j > srow) sv[j] = -1e9f;
    }
    float mt2 = sv[0];
#pragma unroll
    for (int j = 1; j < 16; j++) mt2 = fmaxf(mt2, sv[j]);
    mt2 = fmaxf(mt2, __shfl_xor_sync(0xffffffffu, mt2, 1));
    mt2 = fmaxf(mt2, __shfl_xor_sync(0xffffffffu, mt2, 2));
    const float mnew = fmaxf(mrow, mt2);
    const float corr = __expf(mrow - mnew);
    float sum = 0.f;
#pragma unroll
    for (int j = 0; j < 16; j++) {
      sv[j] = __expf(sv[j] - mnew);
      sum += sv[j];
    }
    sum += __shfl_xor_sync(0xffffffffu, sum, 1);
    sum += __shfl_xor_sync(0xffffffffu, sum, 2);
    lrow = lrow * corr + sum;
    mrow = mnew;
    {
      unsigned* pd = Su + srow * 68 + sseg * 16;
#pragma unroll
      for (int qy = 0; qy < 4; qy++) {
        uint4 u = {f2tf32(sv[4 * qy + 0]), f2tf32(sv[4 * qy + 1]),
                   f2tf32(sv[4 * qy + 2]), f2tf32(sv[4 * qy + 3])};
        *(uint4*)(pd + 4 * qy) = u;
      }
    }
    if (sseg == 0) { corr_s[srow] = corr; l_s[srow] = lrow; }
    __syncthreads();

    // ---- rescale O, O += P @ V ----
    const float cr0 = corr_s[mq + lr];
    const float cr1 = corr_s[mq + 8 + lr];
#pragma unroll
    for (int nt = 0; nt < 4; nt++) {
      oacc[nt][0] *= cr0; oacc[nt][1] *= cr0;
      oacc[nt][2] *= cr1; oacc[nt][3] *= cr1;
    }
#pragma unroll
    for (int ks = 0; ks < 8; ks++) {
      const int kb = ks * 8;
      const unsigned pa0 = Su[(mq + lr) * 68 + kb + lc];
      const unsigned pa1 = Su[(mq + 8 + lr) * 68 + kb + lc];
      const unsigned pa2 = Su[(mq + lr) * 68 + kb + 4 + lc];
      const unsigned pa3 = Su[(mq + 8 + lr) * 68 + kb + 4 + lc];
      const unsigned* Vb = Vf + (ks * 8 + (nq >> 3)) * 68 + lane * 2;
#pragma unroll
      for (int nt = 0; nt < 4; nt++) {
        const uint2 v2 = *(const uint2*)(Vb + nt * 68);
        mma_tf32(oacc[nt][0], oacc[nt][1], oacc[nt][2], oacc[nt][3],
                 pa0, pa1, pa2, pa3, v2.x, v2.y);
      }
    }
  }

  // ---- finalize ----
  const float inv0 = 1.0f / l_s[mq + lr];
  const float inv1 = 1.0f / l_s[mq + 8 + lr];
#pragma unroll
  for (int nt = 0; nt < 4; nt++) {
    const int col = nq + nt * 8 + 2 * lc;
    float* o0 = O + (((size_t)((b * SEQ + q0 + mq + lr) * NHEAD + h)) << 6) + col;
    float* o1 = O + (((size_t)((b * SEQ + q0 + mq + 8 + lr) * NHEAD + h)) << 6) + col;
    float2 w0 = {oacc[nt][0] * inv0, oacc[nt][1] * inv0};
    float2 w1 = {oacc[nt][2] * inv1, oacc[nt][3] * inv1};
    *(float2*)o0 = w0;
    *(float2*)o1 = w1;
  }
}

// ---------------------------------------------------------------------------
// Launch
// ---------------------------------------------------------------------------
extern "C" void kernel_launch(void* const* d_in, const int* in_sizes, int n_in,
                              void* d_out, int out_size) {
  (void)in_sizes; (void)n_in; (void)out_size;
  const float* x      = (const float*)d_in[0];
  const float* Wq     = (const float*)d_in[2];
  const float* bq     = (const float*)d_in[3];
  const float* Wk     = (const float*)d_in[4];
  const float* bk     = (const float*)d_in[5];
  const float* Wv     = (const float*)d_in[6];
  const float* bv     = (const float*)d_in[7];
  const float* Wo     = (const float*)d_in[8];
  const float* bo     = (const float*)d_in[9];
  const float* W1     = (const float*)d_in[10];
  const float* b1     = (const float*)d_in[11];
  const float* W2     = (const float*)d_in[12];
  const float* b2     = (const float*)d_in[13];
  const float* alpha1 = (const float*)d_in[14];
  const float* bias1  = (const float*)d_in[15];
  const float* alpha2 = (const float*)d_in[16];
  const float* bias2  = (const float*)d_in[17];
  float* out = (float*)d_out;

  float *x2, *q, *k, *v, *attn, *xmid, *ff;
  cudaGetSymbolAddress((void**)&x2, g_x2);
  cudaGetSymbolAddress((void**)&q, g_q);
  cudaGetSymbolAddress((void**)&k, g_k);
  cudaGetSymbolAddress((void**)&v, g_v);
  cudaGetSymbolAddress((void**)&attn, g_attn);
  cudaGetSymbolAddress((void**)&xmid, g_xmid);
  cudaGetSymbolAddress((void**)&ff, g_ff);

  static int attn_smem_set = 0;
  if (!attn_smem_set) {
    cudaFuncSetAttribute(flash_attn_tc_kernel,
                         cudaFuncAttributeMaxDynamicSharedMemorySize, ATTN_SMEM);
    attn_smem_set = 1;
  }

  const dim3 gemm_grid(DMODEL / 128, ROWS / 128);        // (8, 64)
  const dim3 qkv_grid(DMODEL / 128, ROWS / 128, 3);      // fused QKV

  layernorm_kernel<<<ROWS, 256>>>(x, alpha1, bias1, x2);
  qkv_kernel<<<qkv_grid, 256>>>(DMODEL, DMODEL, x2,
                                Wq, bq, q, Wk, bk, k, Wv, bv, v);
  flash_attn_tc_kernel<<<dim3(SEQ / 64, NHEAD, BATCH), 256, ATTN_SMEM>>>(q, k, v, attn);
  tgemm_kernel<2><<<gemm_grid, 256>>>(DMODEL, DMODEL, attn, Wo, bo, x, xmid);
  layernorm_kernel<<<ROWS, 256>>>(xmid, alpha2, bias2, x2);
  tgemm_kernel<1><<<gemm_grid, 256>>>(DMODEL, DMODEL, x2, W1, b1, nullptr, ff);
  tgemm_kernel<2><<<gemm_grid, 256>>>(DMODEL, DMODEL, ff, W2, b2, xmid, out);
}

// round 6
// speedup vs baseline: 5.8696x; 1.1318x over previous
#include <cuda_runtime.h>
#include <math.h>

// Problem constants
#define BATCH 4
#define SEQ 2048
#define DMODEL 1024
#define NHEAD 16
#define DK 64
#define ROWS (BATCH * SEQ)   // 8192

// ---------------------------------------------------------------------------
// Scratch (device globals; no allocation allowed)
// ---------------------------------------------------------------------------
__device__ float g_x2[ROWS * DMODEL];
__device__ float g_q[ROWS * DMODEL];
__device__ float g_k[ROWS * DMODEL];
__device__ float g_v[ROWS * DMODEL];
__device__ float g_attn[ROWS * DMODEL];
__device__ float g_xmid[ROWS * DMODEL];
__device__ float g_ff[ROWS * DMODEL];

// ---------------------------------------------------------------------------
// helpers
// ---------------------------------------------------------------------------
__device__ __forceinline__ unsigned f2tf32(float f) {
  unsigned u;
  asm("cvt.rna.tf32.f32 %0, %1;" : "=r"(u) : "f"(f));
  return u;
}

__device__ __forceinline__ void mma_tf32(
    float& c0, float& c1, float& c2, float& c3,
    unsigned a0, unsigned a1, unsigned a2, unsigned a3,
    unsigned b0, unsigned b1) {
  asm("mma.sync.aligned.m16n8k8.row.col.f32.tf32.tf32.f32 "
      "{%0,%1,%2,%3}, {%4,%5,%6,%7}, {%8,%9}, {%0,%1,%2,%3};"
      : "+f"(c0), "+f"(c1), "+f"(c2), "+f"(c3)
      : "r"(a0), "r"(a1), "r"(a2), "r"(a3), "r"(b0), "r"(b1));
}

__device__ __forceinline__ void cp_async16(void* smem_dst, const void* gmem_src) {
  unsigned s = (unsigned)__cvta_generic_to_shared(smem_dst);
  asm volatile("cp.async.ca.shared.global [%0], [%1], 16;\n" ::"r"(s),
               "l"(gmem_src));
}
__device__ __forceinline__ void cp_commit() {
  asm volatile("cp.async.commit_group;\n" ::);
}
template <int N>
__device__ __forceinline__ void cp_wait() {
  asm volatile("cp.async.wait_group %0;\n" ::"n"(N));
}

__device__ __forceinline__ float gelu_f(float v) {
  float t = tanhf(0.7978845608028654f * (v + 0.044715f * v * v * v));
  return 0.5f * v * (1.0f + t);
}

// ---------------------------------------------------------------------------
// LayerNorm
// ---------------------------------------------------------------------------
__global__ void __launch_bounds__(256) layernorm_kernel(
    const float* __restrict__ x, const float* __restrict__ alpha,
    const float* __restrict__ beta, float* __restrict__ y) {
  __shared__ float red[8];
  __shared__ float bcast;
  const int row = blockIdx.x;
  const int tid = threadIdx.x;
  const float* xp = x + (size_t)row * DMODEL;

  float4 v = *(const float4*)(xp + tid * 4);
  float s = v.x + v.y + v.z + v.w;
#pragma unroll
  for (int o = 16; o; o >>= 1) s += __shfl_xor_sync(0xffffffffu, s, o);
  if ((tid & 31) == 0) red[tid >> 5] = s;
  __syncthreads();
  if (tid == 0) {
    float t = 0.f;
#pragma unroll
    for (int i = 0; i < 8; i++) t += red[i];
    bcast = t;
  }
  __syncthreads();
  const float mean = bcast * (1.0f / (float)DMODEL);
  __syncthreads();

  const float dx = v.x - mean, dy = v.y - mean, dz = v.z - mean, dw = v.w - mean;
  float sq = dx * dx + dy * dy + dz * dz + dw * dw;
#pragma unroll
  for (int o = 16; o; o >>= 1) sq += __shfl_xor_sync(0xffffffffu, sq, o);
  if ((tid & 31) == 0) red[tid >> 5] = sq;
  __syncthreads();
  if (tid == 0) {
    float t = 0.f;
#pragma unroll
    for (int i = 0; i < 8; i++) t += red[i];
    bcast = t;
  }
  __syncthreads();
  const float var = bcast * (1.0f / (float)(DMODEL - 1));
  const float sc = 1.0f / (sqrtf(var) + 1e-6f);

  const float4 a4 = *(const float4*)(alpha + tid * 4);
  const float4 b4 = *(const float4*)(beta + tid * 4);
  float4 o4;
  o4.x = a4.x * dx * sc + b4.x;
  o4.y = a4.y * dy * sc + b4.y;
  o4.z = a4.z * dz * sc + b4.z;
  o4.w = a4.w * dw * sc + b4.w;
  *(float4*)(y + (size_t)row * DMODEL + tid * 4) = o4;
}

// ---------------------------------------------------------------------------
// tf32 TC GEMM, cp.async 4-stage pipeline, raw-f32 smem.
// BM=128 BN=128 BK=16, 256 thr = 8 warps (2m x 4n), warp tile 64x32.
// A smem: [m(128)][k stride 20]  (20 % 32 == 4 -> conflict-free frag LDS)
// B smem: [k(16)][n stride 136]  (136 % 32 == 8 -> conflict-free frag LDS)
// mma operands are raw f32 bits (HW uses tf32 subset).
// ---------------------------------------------------------------------------
#define ASTR 20
#define BSTR 136
#define STAGE_WORDS (128 * ASTR + 16 * BSTR)   // 2560 + 2176 = 4736
#define NSTAGE 4
#define GEMM_SMEM (STAGE_WORDS * NSTAGE * 4)   // 75776 bytes

template <int EPI>  // 0=bias, 1=bias+gelu, 2=bias+residual
__device__ __forceinline__ void gemm_body(
    int N, int K,
    const float* __restrict__ A, const float* __restrict__ B,
    const float* __restrict__ bias, const float* __restrict__ res,
    float* __restrict__ C) {
  extern __shared__ float sm[];

  const int tid = threadIdx.x;
  const int cRow = blockIdx.y, cCol = blockIdx.x;
  const int lane = tid & 31, warp = tid >> 5;
  const int lr = lane >> 2, lc = lane & 3;
  const int m0 = (warp & 1) * 64;
  const int n0 = (warp >> 1) * 32;

  // cp.async source/dest indexing
  const int a_row = tid >> 2;            // 0..63 (+64)
  const int a_kq = (tid & 3) << 2;       // 0,4,8,12
  const int b_row = tid >> 5;            // 0..7 (+8)
  const int b_nq = (tid & 31) << 2;      // 0..124

  const float* Ap = A + (size_t)(cRow * 128 + a_row) * K + a_kq;
  const float* Bp = B + (size_t)b_row * N + cCol * 128 + b_nq;

  float acc[4][4][4];
#pragma unroll
  for (int i = 0; i < 4; i++)
#pragma unroll
    for (int j = 0; j < 4; j++)
#pragma unroll
      for (int q = 0; q < 4; q++) acc[i][j][q] = 0.f;

  const int NT = K / 16;

  // issue loads for ktile t into stage s
  auto issue = [&](int s, int t) {
    float* As = sm + s * STAGE_WORDS;
    float* Bs = As + 128 * ASTR;
    const int k0 = t * 16;
    cp_async16(As + a_row * ASTR + a_kq, Ap + k0);
    cp_async16(As + (a_row + 64) * ASTR + a_kq, Ap + (size_t)64 * K + k0);
    cp_async16(Bs + b_row * BSTR + b_nq, Bp + (size_t)k0 * N);
    cp_async16(Bs + (b_row + 8) * BSTR + b_nq, Bp + (size_t)(k0 + 8) * N);
  };

#pragma unroll
  for (int s = 0; s < NSTAGE - 1; s++) {
    issue(s, s);
    cp_commit();
  }

  for (int t = 0; t < NT; t++) {
    cp_wait<NSTAGE - 2>();
    __syncthreads();

    const int s = t & (NSTAGE - 1);
    const float* As = sm + s * STAGE_WORDS;
    const float* Bs = As + 128 * ASTR;
    const unsigned* Au = (const unsigned*)As;
    const unsigned* Bu = (const unsigned*)Bs;

#pragma unroll
    for (int ks = 0; ks < 2; ks++) {
      const int kb = ks * 8;
      unsigned af[4][4], bf[4][2];
#pragma unroll
      for (int mt = 0; mt < 4; mt++) {
        const int m = m0 + mt * 16 + lr;
        af[mt][0] = Au[m * ASTR + kb + lc];
        af[mt][1] = Au[(m + 8) * ASTR + kb + lc];
        af[mt][2] = Au[m * ASTR + kb + 4 + lc];
        af[mt][3] = Au[(m + 8) * ASTR + kb + 4 + lc];
      }
#pragma unroll
      for (int nt = 0; nt < 4; nt++) {
        const int n = n0 + nt * 8 + lr;
        bf[nt][0] = Bu[(kb + lc) * BSTR + n];
        bf[nt][1] = Bu[(kb + 4 + lc) * BSTR + n];
      }
#pragma unroll
      for (int mt = 0; mt < 4; mt++)
#pragma unroll
        for (int nt = 0; nt < 4; nt++)
          mma_tf32(acc[mt][nt][0], acc[mt][nt][1], acc[mt][nt][2], acc[mt][nt][3],
                   af[mt][0], af[mt][1], af[mt][2], af[mt][3],
                   bf[nt][0], bf[nt][1]);
    }

    if (t + NSTAGE - 1 < NT) issue((t + NSTAGE - 1) & (NSTAGE - 1), t + NSTAGE - 1);
    cp_commit();
  }

  // epilogue
#pragma unroll
  for (int mt = 0; mt < 4; mt++) {
    const int r0 = cRow * 128 + m0 + mt * 16 + lr;
#pragma unroll
    for (int nt = 0; nt < 4; nt++) {
      const int col = cCol * 128 + n0 + nt * 8 + 2 * lc;
      const float bx = bias[col], by = bias[col + 1];
      float v0 = acc[mt][nt][0] + bx, v1 = acc[mt][nt][1] + by;
      float v2 = acc[mt][nt][2] + bx, v3 = acc[mt][nt][3] + by;
      if (EPI == 1) { v0 = gelu_f(v0); v1 = gelu_f(v1); v2 = gelu_f(v2); v3 = gelu_f(v3); }
      if (EPI == 2) {
        const float2 r4a = *(const float2*)(res + (size_t)r0 * N + col);
        const float2 r4b = *(const float2*)(res + (size_t)(r0 + 8) * N + col);
        v0 += r4a.x; v1 += r4a.y; v2 += r4b.x; v3 += r4b.y;
      }
      float2 o0 = {v0, v1}, o1 = {v2, v3};
      *(float2*)(C + (size_t)r0 * N + col) = o0;
      *(float2*)(C + (size_t)(r0 + 8) * N + col) = o1;
    }
  }
}

template <int EPI>
__global__ void __launch_bounds__(256) tgemm_kernel(
    int N, int K,
    const float* __restrict__ A, const float* __restrict__ B,
    const float* __restrict__ bias, const float* __restrict__ res,
    float* __restrict__ C) {
  gemm_body<EPI>(N, K, A, B, bias, res, C);
}

// Fused QKV: grid.z selects which projection
__global__ void __launch_bounds__(256) qkv_kernel(
    int N, int K, const float* __restrict__ A,
    const float* __restrict__ Wq, const float* __restrict__ bq, float* __restrict__ q,
    const float* __restrict__ Wk, const float* __restrict__ bk, float* __restrict__ k,
    const float* __restrict__ Wv, const float* __restrict__ bv, float* __restrict__ v) {
  const float* B;
  const float* bias;
  float* C;
  if (blockIdx.z == 0)      { B = Wq; bias = bq; C = q; }
  else if (blockIdx.z == 1) { B = Wk; bias = bk; C = k; }
  else                      { B = Wv; bias = bv; C = v; }
  gemm_body<0>(N, K, A, B, bias, nullptr, C);
}

// ---------------------------------------------------------------------------
// Flash attention (causal), tf32 TC, fragment-packed K/V smem.
// ---------------------------------------------------------------------------
#define SF_BYTES (64 * 68 * 4)          // 17408
#define KF_BYTES (8 * 8 * 68 * 4)       // 17408
#define ATTN_SMEM (SF_BYTES + 2 * KF_BYTES + 512)

__global__ void __launch_bounds__(256) flash_attn_tc_kernel(
    const float* __restrict__ Q, const float* __restrict__ K,
    const float* __restrict__ V, float* __restrict__ O) {
  extern __shared__ char smem_c[];
  float* Sf = (float*)smem_c;
  unsigned* Su = (unsigned*)smem_c;
  unsigned* Kf = (unsigned*)(smem_c + SF_BYTES);
  unsigned* Vf = (unsigned*)(smem_c + SF_BYTES + KF_BYTES);
  float* corr_s = (float*)(smem_c + SF_BYTES + 2 * KF_BYTES);
  float* l_s = corr_s + 64;

  const int qt = blockIdx.x, h = blockIdx.y, b = blockIdx.z;
  const int tid = threadIdx.x;
  const int lane = tid & 31, warp = tid >> 5;
  const int lr = lane >> 2, lc = lane & 3;
  const int mq = (warp >> 1) * 16;
  const int nq = (warp & 1) * 32;
  const int q0 = qt * 64;

#pragma unroll
  for (int i = 0; i < 4; i++) {
    const int idx = tid + i * 256;
    const int r = idx >> 4, d0 = (idx & 15) << 2;
    float4 v4 = *(const float4*)(
        Q + (((size_t)((b * SEQ + q0 + r) * NHEAD + h)) << 6) + d0);
    v4.x *= 0.125f; v4.y *= 0.125f; v4.z *= 0.125f; v4.w *= 0.125f;
    *(float4*)(Sf + r * 68 + d0) = v4;
  }
  __syncthreads();
  unsigned qa[8][4];
#pragma unroll
  for (int ks = 0; ks < 8; ks++) {
    const int c = ks * 8 + lc;
    qa[ks][0] = f2tf32(Sf[(mq + lr) * 68 + c]);
    qa[ks][1] = f2tf32(Sf[(mq + 8 + lr) * 68 + c]);
    qa[ks][2] = f2tf32(Sf[(mq + lr) * 68 + c + 4]);
    qa[ks][3] = f2tf32(Sf[(mq + 8 + lr) * 68 + c + 4]);
  }

  float oacc[4][4];
#pragma unroll
  for (int nt = 0; nt < 4; nt++)
#pragma unroll
    for (int q = 0; q < 4; q++) oacc[nt][q] = 0.f;

  const int srow = tid >> 2, sseg = tid & 3;
  float mrow = -1e30f, lrow = 0.f;

  for (int kt = 0; kt <= qt; kt++) {
    __syncthreads();
#pragma unroll
    for (int i = 0; i < 4; i++) {
      const int idx = tid + i * 256;
      const int r = idx >> 4, d0 = (idx & 15) << 2;
      const size_t g =
          (((size_t)((b * SEQ + kt * 64 + r) * NHEAD + h)) << 6) + d0;
      const float4 kk = *(const float4*)(K + g);
      const float4 vv = *(const float4*)(V + g);
      {
        const int ksb = d0 >> 3;
        const int p = (d0 >> 2) & 1;
        const int nt = r >> 3, lrk = r & 7;
        unsigned* base = Kf + ((ksb * 8 + nt) * 68) + p;
        const int sx = ksb & 3;
        const int l0 = lrk * 4;
        const float w[4] = {kk.x, kk.y, kk.z, kk.w};
#pragma unroll
        for (int j = 0; j < 4; j++)
          base[(l0 + (j ^ sx)) * 2] = f2tf32(w[j]);
      }
      {
        const int ksv = r >> 3;
        const int kc = r & 7;
        const int lcv = kc & 3, p = kc >> 2;
        const int nt = d0 >> 3, lr0 = d0 & 7;
        unsigned* base = Vf + ((ksv * 8 + nt) * 68) + p;
        const float w[4] = {vv.x, vv.y, vv.z, vv.w};
#pragma unroll
        for (int j = 0; j < 4; j++)
          base[((lr0 + j) * 4 + lcv) * 2] = f2tf32(w[j]);
      }
    }
    __syncthreads();

    float sacc[4][4];
#pragma unroll
    for (int nt = 0; nt < 4; nt++)
#pragma unroll
      for (int q = 0; q < 4; q++) sacc[nt][q] = 0.f;
#pragma unroll
    for (int ks = 0; ks < 8; ks++) {
      const unsigned* Kb = Kf + (ks * 8 + (nq >> 3)) * 68 + (lane ^ (ks & 3)) * 2;
#pragma unroll
      for (int nt = 0; nt < 4; nt++) {
        const uint2 kb2 = *(const uint2*)(Kb + nt * 68);
        mma_tf32(sacc[nt][0], sacc[nt][1], sacc[nt][2], sacc[nt][3],
                 qa[ks][0], qa[ks][1], qa[ks][2], qa[ks][3], kb2.x, kb2.y);
      }
    }
#pragma unroll
    for (int nt = 0; nt < 4; nt++) {
      const int col = nq + nt * 8 + 2 * lc;
      float2 s01 = {sacc[nt][0], sacc[nt][1]};
      float2 s23 = {sacc[nt][2], sacc[nt][3]};
      *(float2*)(Sf + (mq + lr) * 68 + col) = s01;
      *(float2*)(Sf + (mq + 8 + lr) * 68 + col) = s23;
    }
    __syncthreads();

    float sv[16];
    {
      const float4* sp = (const float4*)(Sf + srow * 68 + sseg * 16);
      ((float4*)sv)[0] = sp[0];
      ((float4*)sv)[1] = sp[1];
      ((float4*)sv)[2] = sp[2];
      ((float4*)sv)[3] = sp[3];
    }
    if (kt == qt) {
#pragma unroll
      for (int j = 0; j < 16; j++)
        if (sseg * 16 + j > srow) sv[j] = -1e9f;
    }
    float mt2 = sv[0];
#pragma unroll
    for (int j = 1; j < 16; j++) mt2 = fmaxf(mt2, sv[j]);
    mt2 = fmaxf(mt2, __shfl_xor_sync(0xffffffffu, mt2, 1));
    mt2 = fmaxf(mt2, __shfl_xor_sync(0xffffffffu, mt2, 2));
    const float mnew = fmaxf(mrow, mt2);
    const float corr = __expf(mrow - mnew);
    float sum = 0.f;
#pragma unroll
    for (int j = 0; j < 16; j++) {
      sv[j] = __expf(sv[j] - mnew);
      sum += sv[j];
    }
    sum += __shfl_xor_sync(0xffffffffu, sum, 1);
    sum += __shfl_xor_sync(0xffffffffu, sum, 2);
    lrow = lrow * corr + sum;
    mrow = mnew;
    {
      unsigned* pd = Su + srow * 68 + sseg * 16;
#pragma unroll
      for (int qy = 0; qy < 4; qy++) {
        uint4 u = {f2tf32(sv[4 * qy + 0]), f2tf32(sv[4 * qy + 1]),
                   f2tf32(sv[4 * qy + 2]), f2tf32(sv[4 * qy + 3])};
        *(uint4*)(pd + 4 * qy) = u;
      }
    }
    if (sseg == 0) { corr_s[srow] = corr; l_s[srow] = lrow; }
    __syncthreads();

    const float cr0 = corr_s[mq + lr];
    const float cr1 = corr_s[mq + 8 + lr];
#pragma unroll
    for (int nt = 0; nt < 4; nt++) {
      oacc[nt][0] *= cr0; oacc[nt][1] *= cr0;
      oacc[nt][2] *= cr1; oacc[nt][3] *= cr1;
    }
#pragma unroll
    for (int ks = 0; ks < 8; ks++) {
      const int kb = ks * 8;
      const unsigned pa0 = Su[(mq + lr) * 68 + kb + lc];
      const unsigned pa1 = Su[(mq + 8 + lr) * 68 + kb + lc];
      const unsigned pa2 = Su[(mq + lr) * 68 + kb + 4 + lc];
      const unsigned pa3 = Su[(mq + 8 + lr) * 68 + kb + 4 + lc];
      const unsigned* Vb = Vf + (ks * 8 + (nq >> 3)) * 68 + lane * 2;
#pragma unroll
      for (int nt = 0; nt < 4; nt++) {
        const uint2 v2 = *(const uint2*)(Vb + nt * 68);
        mma_tf32(oacc[nt][0], oacc[nt][1], oacc[nt][2], oacc[nt][3],
                 pa0, pa1, pa2, pa3, v2.x, v2.y);
      }
    }
  }

  const float inv0 = 1.0f / l_s[mq + lr];
  const float inv1 = 1.0f / l_s[mq + 8 + lr];
#pragma unroll
  for (int nt = 0; nt < 4; nt++) {
    const int col = nq + nt * 8 + 2 * lc;
    float* o0 = O + (((size_t)((b * SEQ + q0 + mq + lr) * NHEAD + h)) << 6) + col;
    float* o1 = O + (((size_t)((b * SEQ + q0 + mq + 8 + lr) * NHEAD + h)) << 6) + col;
    float2 w0 = {oacc[nt][0] * inv0, oacc[nt][1] * inv0};
    float2 w1 = {oacc[nt][2] * inv1, oacc[nt][3] * inv1};
    *(float2*)o0 = w0;
    *(float2*)o1 = w1;
  }
}

// ---------------------------------------------------------------------------
// Launch
// ---------------------------------------------------------------------------
extern "C" void kernel_launch(void* const* d_in, const int* in_sizes, int n_in,
                              void* d_out, int out_size) {
  (void)in_sizes; (void)n_in; (void)out_size;
  const float* x      = (const float*)d_in[0];
  const float* Wq     = (const float*)d_in[2];
  const float* bq     = (const float*)d_in[3];
  const float* Wk     = (const float*)d_in[4];
  const float* bk     = (const float*)d_in[5];
  const float* Wv     = (const float*)d_in[6];
  const float* bv     = (const float*)d_in[7];
  const float* Wo     = (const float*)d_in[8];
  const float* bo     = (const float*)d_in[9];
  const float* W1     = (const float*)d_in[10];
  const float* b1     = (const float*)d_in[11];
  const float* W2     = (const float*)d_in[12];
  const float* b2     = (const float*)d_in[13];
  const float* alpha1 = (const float*)d_in[14];
  const float* bias1  = (const float*)d_in[15];
  const float* alpha2 = (const float*)d_in[16];
  const float* bias2  = (const float*)d_in[17];
  float* out = (float*)d_out;

  float *x2, *q, *k, *v, *attn, *xmid, *ff;
  cudaGetSymbolAddress((void**)&x2, g_x2);
  cudaGetSymbolAddress((void**)&q, g_q);
  cudaGetSymbolAddress((void**)&k, g_k);
  cudaGetSymbolAddress((void**)&v, g_v);
  cudaGetSymbolAddress((void**)&attn, g_attn);
  cudaGetSymbolAddress((void**)&xmid, g_xmid);
  cudaGetSymbolAddress((void**)&ff, g_ff);

  // idempotent, host-side, safe to call every launch (no static guards)
  cudaFuncSetAttribute(flash_attn_tc_kernel,
                       cudaFuncAttributeMaxDynamicSharedMemorySize, ATTN_SMEM);
  cudaFuncSetAttribute(tgemm_kernel<0>,
                       cudaFuncAttributeMaxDynamicSharedMemorySize, GEMM_SMEM);
  cudaFuncSetAttribute(tgemm_kernel<1>,
                       cudaFuncAttributeMaxDynamicSharedMemorySize, GEMM_SMEM);
  cudaFuncSetAttribute(tgemm_kernel<2>,
                       cudaFuncAttributeMaxDynamicSharedMemorySize, GEMM_SMEM);
  cudaFuncSetAttribute(qkv_kernel,
                       cudaFuncAttributeMaxDynamicSharedMemorySize, GEMM_SMEM);

  const dim3 gemm_grid(DMODEL / 128, ROWS / 128);        // (8, 64)
  const dim3 qkv_grid(DMODEL / 128, ROWS / 128, 3);      // fused QKV

  layernorm_kernel<<<ROWS, 256>>>(x, alpha1, bias1, x2);
  qkv_kernel<<<qkv_grid, 256, GEMM_SMEM>>>(DMODEL, DMODEL, x2,
                                           Wq, bq, q, Wk, bk, k, Wv, bv, v);
  flash_attn_tc_kernel<<<dim3(SEQ / 64, NHEAD, BATCH), 256, ATTN_SMEM>>>(q, k, v, attn);
  tgemm_kernel<2><<<gemm_grid, 256, GEMM_SMEM>>>(DMODEL, DMODEL, attn, Wo, bo, x, xmid);
  layernorm_kernel<<<ROWS, 256>>>(xmid, alpha2, bias2, x2);
  tgemm_kernel<1><<<gemm_grid, 256, GEMM_SMEM>>>(DMODEL, DMODEL, x2, W1, b1, nullptr, ff);
  tgemm_kernel<2><<<gemm_grid, 256, GEMM_SMEM>>>(DMODEL, DMODEL, ff, W2, b2, xmid, out);
}

// round 10
// speedup vs baseline: 8.0307x; 1.3682x over previous
#include <cuda_runtime.h>
#include <cuda_fp16.h>
#include <math.h>
#include <stdint.h>

// Problem constants
#define BATCH 4
#define SEQ 2048
#define DMODEL 1024
#define NHEAD 16
#define ROWS (BATCH * SEQ)   // 8192

// ---------------------------------------------------------------------------
// Scratch (device globals; no allocation allowed)
// ---------------------------------------------------------------------------
__device__ __half g_x2h[ROWS * DMODEL];
__device__ __half g_qh[ROWS * DMODEL];
__device__ __half g_kh[ROWS * DMODEL];
__device__ __half g_vh[ROWS * DMODEL];
__device__ __half g_attnh[ROWS * DMODEL];
__device__ __half g_ffh[ROWS * DMODEL];
__device__ float g_xmid[ROWS * DMODEL];
__device__ __half g_wth[6 * DMODEL * DMODEL];   // transposed fp16 weights [N][K]

// ---------------------------------------------------------------------------
// helpers
// ---------------------------------------------------------------------------
__device__ __forceinline__ unsigned f2tf32(float f) {
  unsigned u;
  asm("cvt.rna.tf32.f32 %0, %1;" : "=r"(u) : "f"(f));
  return u;
}

__device__ __forceinline__ void mma_tf32(
    float& c0, float& c1, float& c2, float& c3,
    unsigned a0, unsigned a1, unsigned a2, unsigned a3,
    unsigned b0, unsigned b1) {
  asm("mma.sync.aligned.m16n8k8.row.col.f32.tf32.tf32.f32 "
      "{%0,%1,%2,%3}, {%4,%5,%6,%7}, {%8,%9}, {%0,%1,%2,%3};"
      : "+f"(c0), "+f"(c1), "+f"(c2), "+f"(c3)
      : "r"(a0), "r"(a1), "r"(a2), "r"(a3), "r"(b0), "r"(b1));
}

__device__ __forceinline__ void mma_f16(
    float& c0, float& c1, float& c2, float& c3,
    unsigned a0, unsigned a1, unsigned a2, unsigned a3,
    unsigned b0, unsigned b1) {
  asm("mma.sync.aligned.m16n8k16.row.col.f32.f16.f16.f32 "
      "{%0,%1,%2,%3}, {%4,%5,%6,%7}, {%8,%9}, {%0,%1,%2,%3};"
      : "+f"(c0), "+f"(c1), "+f"(c2), "+f"(c3)
      : "r"(a0), "r"(a1), "r"(a2), "r"(a3), "r"(b0), "r"(b1));
}

__device__ __forceinline__ void cp_async16(void* smem_dst, const void* gmem_src) {
  unsigned s = (unsigned)__cvta_generic_to_shared(smem_dst);
  asm volatile("cp.async.ca.shared.global [%0], [%1], 16;\n" ::"r"(s),
               "l"(gmem_src));
}
__device__ __forceinline__ void cp_commit() {
  asm volatile("cp.async.commit_group;\n" ::);
}
template <int N>
__device__ __forceinline__ void cp_wait() {
  asm volatile("cp.async.wait_group %0;\n" ::"n"(N));
}

__device__ __forceinline__ float gelu_f(float v) {
  float t = tanhf(0.7978845608028654f * (v + 0.044715f * v * v * v));
  return 0.5f * v * (1.0f + t);
}

// ---------------------------------------------------------------------------
// LayerNorm: f32 in -> fp16 out (feeds GEMM A operands)
// ---------------------------------------------------------------------------
__global__ void __launch_bounds__(256) layernorm_kernel(
    const float* __restrict__ x, const float* __restrict__ alpha,
    const float* __restrict__ beta, __half* __restrict__ y) {
  __shared__ float red[8];
  __shared__ float bcast;
  const int row = blockIdx.x;
  const int tid = threadIdx.x;
  const float* xp = x + (size_t)row * DMODEL;

  float4 v = *(const float4*)(xp + tid * 4);
  float s = v.x + v.y + v.z + v.w;
#pragma unroll
  for (int o = 16; o; o >>= 1) s += __shfl_xor_sync(0xffffffffu, s, o);
  if ((tid & 31) == 0) red[tid >> 5] = s;
  __syncthreads();
  if (tid == 0) {
    float t = 0.f;
#pragma unroll
    for (int i = 0; i < 8; i++) t += red[i];
    bcast = t;
  }
  __syncthreads();
  const float mean = bcast * (1.0f / (float)DMODEL);
  __syncthreads();

  const float dx = v.x - mean, dy = v.y - mean, dz = v.z - mean, dw = v.w - mean;
  float sq = dx * dx + dy * dy + dz * dz + dw * dw;
#pragma unroll
  for (int o = 16; o; o >>= 1) sq += __shfl_xor_sync(0xffffffffu, sq, o);
  if ((tid & 31) == 0) red[tid >> 5] = sq;
  __syncthreads();
  if (tid == 0) {
    float t = 0.f;
#pragma unroll
    for (int i = 0; i < 8; i++) t += red[i];
    bcast = t;
  }
  __syncthreads();
  const float var = bcast * (1.0f / (float)(DMODEL - 1));
  const float sc = 1.0f / (sqrtf(var) + 1e-6f);

  const float4 a4 = *(const float4*)(alpha + tid * 4);
  const float4 b4 = *(const float4*)(beta + tid * 4);
  __half2 h01 = __floats2half2_rn(a4.x * dx * sc + b4.x, a4.y * dy * sc + b4.y);
  __half2 h23 = __floats2half2_rn(a4.z * dz * sc + b4.z, a4.w * dw * sc + b4.w);
  uint2 u = {*(unsigned*)&h01, *(unsigned*)&h23};
  *(uint2*)(y + (size_t)row * DMODEL + tid * 4) = u;
}

// ---------------------------------------------------------------------------
// Weight transpose prepass: Wt[n][k] = (half)W[k][n], six 1024x1024 weights
// ---------------------------------------------------------------------------
__global__ void __launch_bounds__(256) transpose6_kernel(
    const float* __restrict__ Wq, const float* __restrict__ Wk,
    const float* __restrict__ Wv, const float* __restrict__ Wo,
    const float* __restrict__ W1, const float* __restrict__ W2,
    __half* __restrict__ wt) {
  const float* src;
  switch (blockIdx.z) {
    case 0: src = Wq; break;
    case 1: src = Wk; break;
    case 2: src = Wv; break;
    case 3: src = Wo; break;
    case 4: src = W1; break;
    default: src = W2; break;
  }
  __half* dst = wt + (size_t)blockIdx.z * DMODEL * DMODEL;
  __shared__ float tl[32][33];
  const int tx = threadIdx.x, ty = threadIdx.y;
  const int x = blockIdx.x * 32 + tx;
  const int y = blockIdx.y * 32 + ty;
#pragma unroll
  for (int i = 0; i < 32; i += 8)
    tl[ty + i][tx] = src[(size_t)(y + i) * DMODEL + x];
  __syncthreads();
  const int x2 = blockIdx.y * 32 + tx;
  const int y2 = blockIdx.x * 32 + ty;
#pragma unroll
  for (int i = 0; i < 32; i += 8)
    dst[(size_t)(y2 + i) * DMODEL + x2] = __float2half_rn(tl[tx][ty + i]);
}

// ---------------------------------------------------------------------------
// fp16 TC GEMM: C[8192,1024] = A[8192,1024] @ Wt^T (+bias)(+gelu|+residual)
// BM=128 BN=128 BK=32(halves), 256 thr = 8 warps (2m x 4n), warp 64x32.
// m16n8k16, f32 accum. cp.async 4-stage. A/B smem rows padded to 40 halves
// (word-stride 20 -> conflict-free fragment LDS, 16B-aligned rows).
// ---------------------------------------------------------------------------
#define HBK 32
#define HROWB 80                                 // bytes per padded row
#define HA_BYTES (128 * HROWB)                   // 10240
#define HSTAGE_BYTES (2 * HA_BYTES)              // 20480 (A + B)
#define HNSTAGE 4
#define HGEMM_SMEM (HSTAGE_BYTES * HNSTAGE)      // 81920

template <int EPI, typename OutT>  // 0=bias, 1=bias+gelu, 2=bias+residual(f32)
__device__ __forceinline__ void hgemm_body(
    const __half* __restrict__ A, const __half* __restrict__ Bt,
    const float* __restrict__ bias, const float* __restrict__ res,
    OutT* __restrict__ C) {
  extern __shared__ char smc[];
  const int tid = threadIdx.x;
  const int cRow = blockIdx.y, cCol = blockIdx.x;
  const int lane = tid & 31, warp = tid >> 5;
  const int lr = lane >> 2, lc = lane & 3;
  const int m0 = (warp & 1) * 64;
  const int n0 = (warp >> 1) * 32;

  const int row = tid >> 2;        // 0..63 (+64)
  const int ch = tid & 3;          // 16B chunk within 64B row

  const __half* Ap = A + (size_t)(cRow * 128 + row) * DMODEL + ch * 8;
  const __half* Bp = Bt + (size_t)(cCol * 128 + row) * DMODEL + ch * 8;

  float acc[4][4][4];
#pragma unroll
  for (int i = 0; i < 4; i++)
#pragma unroll
    for (int j = 0; j < 4; j++)
#pragma unroll
      for (int q = 0; q < 4; q++) acc[i][j][q] = 0.f;

  const int NT = DMODEL / HBK;  // 32

  auto issue = [&](int s, int t) {
    char* base = smc + s * HSTAGE_BYTES;
    const int k0 = t * HBK;
    cp_async16(base + row * HROWB + ch * 16, Ap + k0);
    cp_async16(base + (row + 64) * HROWB + ch * 16, Ap + (size_t)64 * DMODEL + k0);
    cp_async16(base + HA_BYTES + row * HROWB + ch * 16, Bp + k0);
    cp_async16(base + HA_BYTES + (row + 64) * HROWB + ch * 16,
               Bp + (size_t)64 * DMODEL + k0);
  };

#pragma unroll
  for (int s = 0; s < HNSTAGE - 1; s++) { issue(s, s); cp_commit(); }

  for (int t = 0; t < NT; t++) {
    cp_wait<HNSTAGE - 2>();
    __syncthreads();

    const char* base = smc + (t & (HNSTAGE - 1)) * HSTAGE_BYTES;
    const unsigned* Au = (const unsigned*)base;
    const unsigned* Bu = (const unsigned*)(base + HA_BYTES);

#pragma unroll
    for (int ks = 0; ks < 2; ks++) {
      const int kb = ks * 8;
      unsigned af[4][4], bf[4][2];
#pragma unroll
      for (int mt = 0; mt < 4; mt++) {
        const int m = m0 + mt * 16 + lr;
        af[mt][0] = Au[m * 20 + kb + lc];
        af[mt][1] = Au[(m + 8) * 20 + kb + lc];
        af[mt][2] = Au[m * 20 + kb + 4 + lc];
        af[mt][3] = Au[(m + 8) * 20 + kb + 4 + lc];
      }
#pragma unroll
      for (int nt = 0; nt < 4; nt++) {
        const int n = n0 + nt * 8 + lr;
        bf[nt][0] = Bu[n * 20 + kb + lc];
        bf[nt][1] = Bu[n * 20 + kb + 4 + lc];
      }
#pragma unroll
      for (int mt = 0; mt < 4; mt++)
#pragma unroll
        for (int nt = 0; nt < 4; nt++)
          mma_f16(acc[mt][nt][0], acc[mt][nt][1], acc[mt][nt][2], acc[mt][nt][3],
                  af[mt][0], af[mt][1], af[mt][2], af[mt][3],
                  bf[nt][0], bf[nt][1]);
    }

    if (t + HNSTAGE - 1 < NT)
      issue((t + HNSTAGE - 1) & (HNSTAGE - 1), t + HNSTAGE - 1);
    cp_commit();
  }

  // epilogue
#pragma unroll
  for (int mt = 0; mt < 4; mt++) {
    const int r0 = cRow * 128 + m0 + mt * 16 + lr;
#pragma unroll
    for (int nt = 0; nt < 4; nt++) {
      const int col = cCol * 128 + n0 + nt * 8 + 2 * lc;
      const float bx = bias[col], by = bias[col + 1];
      float v0 = acc[mt][nt][0] + bx, v1 = acc[mt][nt][1] + by;
      float v2 = acc[mt][nt][2] + bx, v3 = acc[mt][nt][3] + by;
      if (EPI == 1) { v0 = gelu_f(v0); v1 = gelu_f(v1); v2 = gelu_f(v2); v3 = gelu_f(v3); }
      if (EPI == 2) {
        const float2 r4a = *(const float2*)(res + (size_t)r0 * DMODEL + col);
        const float2 r4b = *(const float2*)(res + (size_t)(r0 + 8) * DMODEL + col);
        v0 += r4a.x; v1 += r4a.y; v2 += r4b.x; v3 += r4b.y;
      }
      if (sizeof(OutT) == 2) {
        __half2 h0 = __floats2half2_rn(v0, v1);
        __half2 h1 = __floats2half2_rn(v2, v3);
        *(__half2*)((__half*)C + (size_t)r0 * DMODEL + col) = h0;
        *(__half2*)((__half*)C + (size_t)(r0 + 8) * DMODEL + col) = h1;
      } else {
        float2 o0 = {v0, v1}, o1 = {v2, v3};
        *(float2*)((float*)C + (size_t)r0 * DMODEL + col) = o0;
        *(float2*)((float*)C + (size_t)(r0 + 8) * DMODEL + col) = o1;
      }
    }
  }
}

template <int EPI, typename OutT>
__global__ void __launch_bounds__(256) hgemm_kernel(
    const __half* __restrict__ A, const __half* __restrict__ Bt,
    const float* __restrict__ bias, const float* __restrict__ res,
    OutT* __restrict__ C) {
  hgemm_body<EPI, OutT>(A, Bt, bias, res, C);
}

__global__ void __launch_bounds__(256) hqkv_kernel(
    const __half* __restrict__ A, const __half* __restrict__ wt,
    const float* __restrict__ bq, __half* __restrict__ q,
    const float* __restrict__ bk, __half* __restrict__ k,
    const float* __restrict__ bv, __half* __restrict__ v) {
  const __half* Bt;
  const float* bias;
  __half* C;
  if (blockIdx.z == 0)      { Bt = wt;                               bias = bq; C = q; }
  else if (blockIdx.z == 1) { Bt = wt + (size_t)DMODEL * DMODEL;     bias = bk; C = k; }
  else                      { Bt = wt + (size_t)2 * DMODEL * DMODEL; bias = bv; C = v; }
  hgemm_body<0, __half>(A, Bt, bias, nullptr, C);
}

// ---------------------------------------------------------------------------
// Flash attention (causal), tf32 mma.sync, fragment-packed K/V smem.
// Inputs/outputs fp16 (converted at load/store); internal math unchanged.
// ---------------------------------------------------------------------------
#define SF_BYTES (64 * 68 * 4)
#define KF_BYTES (8 * 8 * 68 * 4)
#define ATTN_SMEM (SF_BYTES + 2 * KF_BYTES + 512)

__global__ void __launch_bounds__(256) flash_attn_tc_kernel(
    const __half* __restrict__ Q, const __half* __restrict__ K,
    const __half* __restrict__ V, __half* __restrict__ O) {
  extern __shared__ char smem_c[];
  float* Sf = (float*)smem_c;
  unsigned* Su = (unsigned*)smem_c;
  unsigned* Kf = (unsigned*)(smem_c + SF_BYTES);
  unsigned* Vf = (unsigned*)(smem_c + SF_BYTES + KF_BYTES);
  float* corr_s = (float*)(smem_c + SF_BYTES + 2 * KF_BYTES);
  float* l_s = corr_s + 64;

  const int qt = blockIdx.x, h = blockIdx.y, b = blockIdx.z;
  const int tid = threadIdx.x;
  const int lane = tid & 31, warp = tid >> 5;
  const int lr = lane >> 2, lc = lane & 3;
  const int mq = (warp >> 1) * 16;
  const int nq = (warp & 1) * 32;
  const int q0 = qt * 64;

#pragma unroll
  for (int i = 0; i < 4; i++) {
    const int idx = tid + i * 256;
    const int r = idx >> 4, d0 = (idx & 15) << 2;
    const uint2 hu = *(const uint2*)(
        Q + (((size_t)((b * SEQ + q0 + r) * NHEAD + h)) << 6) + d0);
    float2 f01 = __half22float2(*(const __half2*)&hu.x);
    float2 f23 = __half22float2(*(const __half2*)&hu.y);
    float4 v4 = {f01.x * 0.125f, f01.y * 0.125f, f23.x * 0.125f, f23.y * 0.125f};
    *(float4*)(Sf + r * 68 + d0) = v4;
  }
  __syncthreads();
  unsigned qa[8][4];
#pragma unroll
  for (int ks = 0; ks < 8; ks++) {
    const int c = ks * 8 + lc;
    qa[ks][0] = f2tf32(Sf[(mq + lr) * 68 + c]);
    qa[ks][1] = f2tf32(Sf[(mq + 8 + lr) * 68 + c]);
    qa[ks][2] = f2tf32(Sf[(mq + lr) * 68 + c + 4]);
    qa[ks][3] = f2tf32(Sf[(mq + 8 + lr) * 68 + c + 4]);
  }

  float oacc[4][4];
#pragma unroll
  for (int nt = 0; nt < 4; nt++)
#pragma unroll
    for (int q = 0; q < 4; q++) oacc[nt][q] = 0.f;

  const int srow = tid >> 2, sseg = tid & 3;
  float mrow = -1e30f, lrow2 = 0.f;

  for (int kt = 0; kt <= qt; kt++) {
    __syncthreads();
#pragma unroll
    for (int i = 0; i < 4; i++) {
      const int idx = tid + i * 256;
      const int r = idx >> 4, d0 = (idx & 15) << 2;
      const size_t g =
          (((size_t)((b * SEQ + kt * 64 + r) * NHEAD + h)) << 6) + d0;
      const uint2 ku = *(const uint2*)(K + g);
      const uint2 vu = *(const uint2*)(V + g);
      const float2 k01 = __half22float2(*(const __half2*)&ku.x);
      const float2 k23 = __half22float2(*(const __half2*)&ku.y);
      const float2 v01 = __half22float2(*(const __half2*)&vu.x);
      const float2 v23 = __half22float2(*(const __half2*)&vu.y);
      {
        const int ksb = d0 >> 3;
        const int p = (d0 >> 2) & 1;
        const int nt = r >> 3, lrk = r & 7;
        unsigned* base = Kf + ((ksb * 8 + nt) * 68) + p;
        const int sx = ksb & 3;
        const int l0 = lrk * 4;
        const float w[4] = {k01.x, k01.y, k23.x, k23.y};
#pragma unroll
        for (int j = 0; j < 4; j++)
          base[(l0 + (j ^ sx)) * 2] = f2tf32(w[j]);
      }
      {
        const int ksv = r >> 3;
        const int kc = r & 7;
        const int lcv = kc & 3, p = kc >> 2;
        const int nt = d0 >> 3, lr0 = d0 & 7;
        unsigned* base = Vf + ((ksv * 8 + nt) * 68) + p;
        const float w[4] = {v01.x, v01.y, v23.x, v23.y};
#pragma unroll
        for (int j = 0; j < 4; j++)
          base[((lr0 + j) * 4 + lcv) * 2] = f2tf32(w[j]);
      }
    }
    __syncthreads();

    float sacc[4][4];
#pragma unroll
    for (int nt = 0; nt < 4; nt++)
#pragma unroll
      for (int q = 0; q < 4; q++) sacc[nt][q] = 0.f;
#pragma unroll
    for (int ks = 0; ks < 8; ks++) {
      const unsigned* Kb = Kf + (ks * 8 + (nq >> 3)) * 68 + (lane ^ (ks & 3)) * 2;
#pragma unroll
      for (int nt = 0; nt < 4; nt++) {
        const uint2 kb2 = *(const uint2*)(Kb + nt * 68);
        mma_tf32(sacc[nt][0], sacc[nt][1], sacc[nt][2], sacc[nt][3],
                 qa[ks][0], qa[ks][1], qa[ks][2], qa[ks][3], kb2.x, kb2.y);
      }
    }
#pragma unroll
    for (int nt = 0; nt < 4; nt++) {
      const int col = nq + nt * 8 + 2 * lc;
      float2 s01 = {sacc[nt][0], sacc[nt][1]};
      float2 s23 = {sacc[nt][2], sacc[nt][3]};
      *(float2*)(Sf + (mq + lr) * 68 + col) = s01;
      *(float2*)(Sf + (mq + 8 + lr) * 68 + col) = s23;
    }
    __syncthreads();

    float sv[16];
    {
      const float4* sp = (const float4*)(Sf + srow * 68 + sseg * 16);
      ((float4*)sv)[0] = sp[0];
      ((float4*)sv)[1] = sp[1];
      ((float4*)sv)[2] = sp[2];
      ((float4*)sv)[3] = sp[3];
    }
    if (kt == qt) {
#pragma unroll
      for (int j = 0; j < 16; j++)
        if (sseg * 16 + j > srow) sv[j] = -1e9f;
    }
    float mt2 = sv[0];
#pragma unroll
    for (int j = 1; j < 16; j++) mt2 = fmaxf(mt2, sv[j]);
    mt2 = fmaxf(mt2, __shfl_xor_sync(0xffffffffu, mt2, 1));
    mt2 = fmaxf(mt2, __shfl_xor_sync(0xffffffffu, mt2, 2));
    const float mnew = fmaxf(mrow, mt2);
    const float corr = __expf(mrow - mnew);
    float sum = 0.f;
#pragma unroll
    for (int j = 0; j < 16; j++) {
      sv[j] = __expf(sv[j] - mnew);
      sum += sv[j];
    }
    sum += __shfl_xor_sync(0xffffffffu, sum, 1);
    sum += __shfl_xor_sync(0xffffffffu, sum, 2);
    lrow2 = lrow2 * corr + sum;
    mrow = mnew;
    {
      unsigned* pd = Su + srow * 68 + sseg * 16;
#pragma unroll
      for (int qy = 0; qy < 4; qy++) {
        uint4 u = {f2tf32(sv[4 * qy + 0]), f2tf32(sv[4 * qy + 1]),
                   f2tf32(sv[4 * qy + 2]), f2tf32(sv[4 * qy + 3])};
        *(uint4*)(pd + 4 * qy) = u;
      }
    }
    if (sseg == 0) { corr_s[srow] = corr; l_s[srow] = lrow2; }
    __syncthreads();

    const float cr0 = corr_s[mq + lr];
    const float cr1 = corr_s[mq + 8 + lr];
#pragma unroll
    for (int nt = 0; nt < 4; nt++) {
      oacc[nt][0] *= cr0; oacc[nt][1] *= cr0;
      oacc[nt][2] *= cr1; oacc[nt][3] *= cr1;
    }
#pragma unroll
    for (int ks = 0; ks < 8; ks++) {
      const int kb = ks * 8;
      const unsigned pa0 = Su[(mq + lr) * 68 + kb + lc];
      const unsigned pa1 = Su[(mq + 8 + lr) * 68 + kb + lc];
      const unsigned pa2 = Su[(mq + lr) * 68 + kb + 4 + lc];
      const unsigned pa3 = Su[(mq + 8 + lr) * 68 + kb + 4 + lc];
      const unsigned* Vb = Vf + (ks * 8 + (nq >> 3)) * 68 + lane * 2;
#pragma unroll
      for (int nt = 0; nt < 4; nt++) {
        const uint2 v2 = *(const uint2*)(Vb + nt * 68);
        mma_tf32(oacc[nt][0], oacc[nt][1], oacc[nt][2], oacc[nt][3],
                 pa0, pa1, pa2, pa3, v2.x, v2.y);
      }
    }
  }

  const float inv0 = 1.0f / l_s[mq + lr];
  const float inv1 = 1.0f / l_s[mq + 8 + lr];
#pragma unroll
  for (int nt = 0; nt < 4; nt++) {
    const int col = nq + nt * 8 + 2 * lc;
    __half* o0 = O + (((size_t)((b * SEQ + q0 + mq + lr) * NHEAD + h)) << 6) + col;
    __half* o1 = O + (((size_t)((b * SEQ + q0 + mq + 8 + lr) * NHEAD + h)) << 6) + col;
    *(__half2*)o0 = __floats2half2_rn(oacc[nt][0] * inv0, oacc[nt][1] * inv0);
    *(__half2*)o1 = __floats2half2_rn(oacc[nt][2] * inv1, oacc[nt][3] * inv1);
  }
}

// ---------------------------------------------------------------------------
// Launch
// ---------------------------------------------------------------------------
extern "C" void kernel_launch(void* const* d_in, const int* in_sizes, int n_in,
                              void* d_out, int out_size) {
  (void)in_sizes; (void)n_in; (void)out_size;
  const float* x      = (const float*)d_in[0];
  const float* Wq     = (const float*)d_in[2];
  const float* bq     = (const float*)d_in[3];
  const float* Wk     = (const float*)d_in[4];
  const float* bk     = (const float*)d_in[5];
  const float* Wv     = (const float*)d_in[6];
  const float* bv     = (const float*)d_in[7];
  const float* Wo     = (const float*)d_in[8];
  const float* bo     = (const float*)d_in[9];
  const float* W1     = (const float*)d_in[10];
  const float* b1     = (const float*)d_in[11];
  const float* W2     = (const float*)d_in[12];
  const float* b2     = (const float*)d_in[13];
  const float* alpha1 = (const float*)d_in[14];
  const float* bias1  = (const float*)d_in[15];
  const float* alpha2 = (const float*)d_in[16];
  const float* bias2  = (const float*)d_in[17];
  float* out = (float*)d_out;

  __half *x2h, *qh, *kh, *vh, *attnh, *ffh, *wth;
  float* xmid;
  cudaGetSymbolAddress((void**)&x2h, g_x2h);
  cudaGetSymbolAddress((void**)&qh, g_qh);
  cudaGetSymbolAddress((void**)&kh, g_kh);
  cudaGetSymbolAddress((void**)&vh, g_vh);
  cudaGetSymbolAddress((void**)&attnh, g_attnh);
  cudaGetSymbolAddress((void**)&ffh, g_ffh);
  cudaGetSymbolAddress((void**)&xmid, g_xmid);
  cudaGetSymbolAddress((void**)&wth, g_wth);

  cudaFuncSetAttribute(flash_attn_tc_kernel,
                       cudaFuncAttributeMaxDynamicSharedMemorySize, ATTN_SMEM);
  cudaFuncSetAttribute(hgemm_kernel<1, __half>,
                       cudaFuncAttributeMaxDynamicSharedMemorySize, HGEMM_SMEM);
  cudaFuncSetAttribute(hgemm_kernel<2, float>,
                       cudaFuncAttributeMaxDynamicSharedMemorySize, HGEMM_SMEM);
  cudaFuncSetAttribute(hqkv_kernel,
                       cudaFuncAttributeMaxDynamicSharedMemorySize, HGEMM_SMEM);

  const dim3 gemm_grid(DMODEL / 128, ROWS / 128);      // (8, 64)
  const dim3 qkv_grid(DMODEL / 128, ROWS / 128, 3);

  transpose6_kernel<<<dim3(32, 32, 6), dim3(32, 8)>>>(Wq, Wk, Wv, Wo, W1, W2, wth);
  layernorm_kernel<<<ROWS, 256>>>(x, alpha1, bias1, x2h);
  hqkv_kernel<<<qkv_grid, 256, HGEMM_SMEM>>>(x2h, wth, bq, qh, bk, kh, bv, vh);
  flash_attn_tc_kernel<<<dim3(SEQ / 64, NHEAD, BATCH), 256, ATTN_SMEM>>>(
      qh, kh, vh, attnh);
  hgemm_kernel<2, float><<<gemm_grid, 256, HGEMM_SMEM>>>(
      attnh, wth + (size_t)3 * DMODEL * DMODEL, bo, x, xmid);
  layernorm_kernel<<<ROWS, 256>>>(xmid, alpha2, bias2, x2h);
  hgemm_kernel<1, __half><<<gemm_grid, 256, HGEMM_SMEM>>>(
      x2h, wth + (size_t)4 * DMODEL * DMODEL, b1, nullptr, ffh);
  hgemm_kernel<2, float><<<gemm_grid, 256, HGEMM_SMEM>>>(
      ffh, wth + (size_t)5 * DMODEL * DMODEL, b2, xmid, out);
}

// round 11
// speedup vs baseline: 10.0597x; 1.2527x over previous
#include <cuda_runtime.h>
#include <cuda_fp16.h>
#include <math.h>
#include <stdint.h>

// Problem constants
#define BATCH 4
#define SEQ 2048
#define DMODEL 1024
#define NHEAD 16
#define ROWS (BATCH * SEQ)   // 8192

// ---------------------------------------------------------------------------
// Scratch (device globals; no allocation allowed)
// ---------------------------------------------------------------------------
__device__ __half g_x2h[ROWS * DMODEL];
__device__ __half g_qh[ROWS * DMODEL];
__device__ __half g_kh[ROWS * DMODEL];
__device__ __half g_vh[ROWS * DMODEL];
__device__ __half g_attnh[ROWS * DMODEL];
__device__ __half g_ffh[ROWS * DMODEL];
__device__ float g_xmid[ROWS * DMODEL];
__device__ __half g_wth[6 * DMODEL * DMODEL];   // transposed fp16 weights [N][K]

// ---------------------------------------------------------------------------
// helpers
// ---------------------------------------------------------------------------
__device__ __forceinline__ void mma_f16(
    float& c0, float& c1, float& c2, float& c3,
    unsigned a0, unsigned a1, unsigned a2, unsigned a3,
    unsigned b0, unsigned b1) {
  asm("mma.sync.aligned.m16n8k16.row.col.f32.f16.f16.f32 "
      "{%0,%1,%2,%3}, {%4,%5,%6,%7}, {%8,%9}, {%0,%1,%2,%3};"
      : "+f"(c0), "+f"(c1), "+f"(c2), "+f"(c3)
      : "r"(a0), "r"(a1), "r"(a2), "r"(a3), "r"(b0), "r"(b1));
}

__device__ __forceinline__ void ldsm_x4(uint32_t& r0, uint32_t& r1,
                                        uint32_t& r2, uint32_t& r3, uint32_t a) {
  asm volatile("ldmatrix.sync.aligned.m8n8.x4.shared.b16 {%0,%1,%2,%3}, [%4];"
               : "=r"(r0), "=r"(r1), "=r"(r2), "=r"(r3) : "r"(a));
}
__device__ __forceinline__ void ldsm_x4_t(uint32_t& r0, uint32_t& r1,
                                          uint32_t& r2, uint32_t& r3, uint32_t a) {
  asm volatile("ldmatrix.sync.aligned.m8n8.x4.trans.shared.b16 {%0,%1,%2,%3}, [%4];"
               : "=r"(r0), "=r"(r1), "=r"(r2), "=r"(r3) : "r"(a));
}

__device__ __forceinline__ void cp_async16(void* smem_dst, const void* gmem_src) {
  unsigned s = (unsigned)__cvta_generic_to_shared(smem_dst);
  asm volatile("cp.async.ca.shared.global [%0], [%1], 16;\n" ::"r"(s),
               "l"(gmem_src));
}
__device__ __forceinline__ void cp_commit() {
  asm volatile("cp.async.commit_group;\n" ::);
}
template <int N>
__device__ __forceinline__ void cp_wait() {
  asm volatile("cp.async.wait_group %0;\n" ::"n"(N));
}

__device__ __forceinline__ float gelu_f(float v) {
  float t = tanhf(0.7978845608028654f * (v + 0.044715f * v * v * v));
  return 0.5f * v * (1.0f + t);
}

// ---------------------------------------------------------------------------
// LayerNorm: f32 in -> fp16 out
// ---------------------------------------------------------------------------
__global__ void __launch_bounds__(256) layernorm_kernel(
    const float* __restrict__ x, const float* __restrict__ alpha,
    const float* __restrict__ beta, __half* __restrict__ y) {
  __shared__ float red[8];
  __shared__ float bcast;
  const int row = blockIdx.x;
  const int tid = threadIdx.x;
  const float* xp = x + (size_t)row * DMODEL;

  float4 v = *(const float4*)(xp + tid * 4);
  float s = v.x + v.y + v.z + v.w;
#pragma unroll
  for (int o = 16; o; o >>= 1) s += __shfl_xor_sync(0xffffffffu, s, o);
  if ((tid & 31) == 0) red[tid >> 5] = s;
  __syncthreads();
  if (tid == 0) {
    float t = 0.f;
#pragma unroll
    for (int i = 0; i < 8; i++) t += red[i];
    bcast = t;
  }
  __syncthreads();
  const float mean = bcast * (1.0f / (float)DMODEL);
  __syncthreads();

  const float dx = v.x - mean, dy = v.y - mean, dz = v.z - mean, dw = v.w - mean;
  float sq = dx * dx + dy * dy + dz * dz + dw * dw;
#pragma unroll
  for (int o = 16; o; o >>= 1) sq += __shfl_xor_sync(0xffffffffu, sq, o);
  if ((tid & 31) == 0) red[tid >> 5] = sq;
  __syncthreads();
  if (tid == 0) {
    float t = 0.f;
#pragma unroll
    for (int i = 0; i < 8; i++) t += red[i];
    bcast = t;
  }
  __syncthreads();
  const float var = bcast * (1.0f / (float)(DMODEL - 1));
  const float sc = 1.0f / (sqrtf(var) + 1e-6f);

  const float4 a4 = *(const float4*)(alpha + tid * 4);
  const float4 b4 = *(const float4*)(beta + tid * 4);
  __half2 h01 = __floats2half2_rn(a4.x * dx * sc + b4.x, a4.y * dy * sc + b4.y);
  __half2 h23 = __floats2half2_rn(a4.z * dz * sc + b4.z, a4.w * dw * sc + b4.w);
  uint2 u = {*(unsigned*)&h01, *(unsigned*)&h23};
  *(uint2*)(y + (size_t)row * DMODEL + tid * 4) = u;
}

// ---------------------------------------------------------------------------
// Weight transpose prepass: Wt[n][k] = (half)W[k][n]
// ---------------------------------------------------------------------------
__global__ void __launch_bounds__(256) transpose6_kernel(
    const float* __restrict__ Wq, const float* __restrict__ Wk,
    const float* __restrict__ Wv, const float* __restrict__ Wo,
    const float* __restrict__ W1, const float* __restrict__ W2,
    __half* __restrict__ wt) {
  const float* src;
  switch (blockIdx.z) {
    case 0: src = Wq; break;
    case 1: src = Wk; break;
    case 2: src = Wv; break;
    case 3: src = Wo; break;
    case 4: src = W1; break;
    default: src = W2; break;
  }
  __half* dst = wt + (size_t)blockIdx.z * DMODEL * DMODEL;
  __shared__ float tl[32][33];
  const int tx = threadIdx.x, ty = threadIdx.y;
  const int x = blockIdx.x * 32 + tx;
  const int y = blockIdx.y * 32 + ty;
#pragma unroll
  for (int i = 0; i < 32; i += 8)
    tl[ty + i][tx] = src[(size_t)(y + i) * DMODEL + x];
  __syncthreads();
  const int x2 = blockIdx.y * 32 + tx;
  const int y2 = blockIdx.x * 32 + ty;
#pragma unroll
  for (int i = 0; i < 32; i += 8)
    dst[(size_t)(y2 + i) * DMODEL + x2] = __float2half_rn(tl[tx][ty + i]);
}

// ---------------------------------------------------------------------------
// fp16 TC GEMM (unchanged from R10, proven)
// ---------------------------------------------------------------------------
#define HBK 32
#define HROWB 80
#define HA_BYTES (128 * HROWB)
#define HSTAGE_BYTES (2 * HA_BYTES)
#define HNSTAGE 4
#define HGEMM_SMEM (HSTAGE_BYTES * HNSTAGE)

template <int EPI, typename OutT>
__device__ __forceinline__ void hgemm_body(
    const __half* __restrict__ A, const __half* __restrict__ Bt,
    const float* __restrict__ bias, const float* __restrict__ res,
    OutT* __restrict__ C) {
  extern __shared__ char smc[];
  const int tid = threadIdx.x;
  const int cRow = blockIdx.y, cCol = blockIdx.x;
  const int lane = tid & 31, warp = tid >> 5;
  const int lr = lane >> 2, lc = lane & 3;
  const int m0 = (warp & 1) * 64;
  const int n0 = (warp >> 1) * 32;

  const int row = tid >> 2;
  const int ch = tid & 3;

  const __half* Ap = A + (size_t)(cRow * 128 + row) * DMODEL + ch * 8;
  const __half* Bp = Bt + (size_t)(cCol * 128 + row) * DMODEL + ch * 8;

  float acc[4][4][4];
#pragma unroll
  for (int i = 0; i < 4; i++)
#pragma unroll
    for (int j = 0; j < 4; j++)
#pragma unroll
      for (int q = 0; q < 4; q++) acc[i][j][q] = 0.f;

  const int NT = DMODEL / HBK;

  auto issue = [&](int s, int t) {
    char* base = smc + s * HSTAGE_BYTES;
    const int k0 = t * HBK;
    cp_async16(base + row * HROWB + ch * 16, Ap + k0);
    cp_async16(base + (row + 64) * HROWB + ch * 16, Ap + (size_t)64 * DMODEL + k0);
    cp_async16(base + HA_BYTES + row * HROWB + ch * 16, Bp + k0);
    cp_async16(base + HA_BYTES + (row + 64) * HROWB + ch * 16,
               Bp + (size_t)64 * DMODEL + k0);
  };

#pragma unroll
  for (int s = 0; s < HNSTAGE - 1; s++) { issue(s, s); cp_commit(); }

  for (int t = 0; t < NT; t++) {
    cp_wait<HNSTAGE - 2>();
    __syncthreads();

    const char* base = smc + (t & (HNSTAGE - 1)) * HSTAGE_BYTES;
    const unsigned* Au = (const unsigned*)base;
    const unsigned* Bu = (const unsigned*)(base + HA_BYTES);

#pragma unroll
    for (int ks = 0; ks < 2; ks++) {
      const int kb = ks * 8;
      unsigned af[4][4], bf[4][2];
#pragma unroll
      for (int mt = 0; mt < 4; mt++) {
        const int m = m0 + mt * 16 + lr;
        af[mt][0] = Au[m * 20 + kb + lc];
        af[mt][1] = Au[(m + 8) * 20 + kb + lc];
        af[mt][2] = Au[m * 20 + kb + 4 + lc];
        af[mt][3] = Au[(m + 8) * 20 + kb + 4 + lc];
      }
#pragma unroll
      for (int nt = 0; nt < 4; nt++) {
        const int n = n0 + nt * 8 + lr;
        bf[nt][0] = Bu[n * 20 + kb + lc];
        bf[nt][1] = Bu[n * 20 + kb + 4 + lc];
      }
#pragma unroll
      for (int mt = 0; mt < 4; mt++)
#pragma unroll
        for (int nt = 0; nt < 4; nt++)
          mma_f16(acc[mt][nt][0], acc[mt][nt][1], acc[mt][nt][2], acc[mt][nt][3],
                  af[mt][0], af[mt][1], af[mt][2], af[mt][3],
                  bf[nt][0], bf[nt][1]);
    }

    if (t + HNSTAGE - 1 < NT)
      issue((t + HNSTAGE - 1) & (HNSTAGE - 1), t + HNSTAGE - 1);
    cp_commit();
  }

#pragma unroll
  for (int mt = 0; mt < 4; mt++) {
    const int r0 = cRow * 128 + m0 + mt * 16 + lr;
#pragma unroll
    for (int nt = 0; nt < 4; nt++) {
      const int col = cCol * 128 + n0 + nt * 8 + 2 * lc;
      const float bx = bias[col], by = bias[col + 1];
      float v0 = acc[mt][nt][0] + bx, v1 = acc[mt][nt][1] + by;
      float v2 = acc[mt][nt][2] + bx, v3 = acc[mt][nt][3] + by;
      if (EPI == 1) { v0 = gelu_f(v0); v1 = gelu_f(v1); v2 = gelu_f(v2); v3 = gelu_f(v3); }
      if (EPI == 2) {
        const float2 r4a = *(const float2*)(res + (size_t)r0 * DMODEL + col);
        const float2 r4b = *(const float2*)(res + (size_t)(r0 + 8) * DMODEL + col);
        v0 += r4a.x; v1 += r4a.y; v2 += r4b.x; v3 += r4b.y;
      }
      if (sizeof(OutT) == 2) {
        __half2 h0 = __floats2half2_rn(v0, v1);
        __half2 h1 = __floats2half2_rn(v2, v3);
        *(__half2*)((__half*)C + (size_t)r0 * DMODEL + col) = h0;
        *(__half2*)((__half*)C + (size_t)(r0 + 8) * DMODEL + col) = h1;
      } else {
        float2 o0 = {v0, v1}, o1 = {v2, v3};
        *(float2*)((float*)C + (size_t)r0 * DMODEL + col) = o0;
        *(float2*)((float*)C + (size_t)(r0 + 8) * DMODEL + col) = o1;
      }
    }
  }
}

template <int EPI, typename OutT>
__global__ void __launch_bounds__(256) hgemm_kernel(
    const __half* __restrict__ A, const __half* __restrict__ Bt,
    const float* __restrict__ bias, const float* __restrict__ res,
    OutT* __restrict__ C) {
  hgemm_body<EPI, OutT>(A, Bt, bias, res, C);
}

__global__ void __launch_bounds__(256) hqkv_kernel(
    const __half* __restrict__ A, const __half* __restrict__ wt,
    const float* __restrict__ bq, __half* __restrict__ q,
    const float* __restrict__ bk, __half* __restrict__ k,
    const float* __restrict__ bv, __half* __restrict__ v) {
  const __half* Bt;
  const float* bias;
  __half* C;
  if (blockIdx.z == 0)      { Bt = wt;                               bias = bq; C = q; }
  else if (blockIdx.z == 1) { Bt = wt + (size_t)DMODEL * DMODEL;     bias = bk; C = k; }
  else                      { Bt = wt + (size_t)2 * DMODEL * DMODEL; bias = bv; C = v; }
  hgemm_body<0, __half>(A, Bt, bias, nullptr, C);
}

// ---------------------------------------------------------------------------
// Flash attention (causal), fp16 m16n8k16 + ldmatrix + cp.async 2-stage KV.
// 64q x 64k tile, DK=64, 256 thr = 8 warps (4m x 2n).
// smem (bytes): Qf[64][72]h @0 | Kf[2][64][72]h @9216 | Vf[2][64][72]h @27648
//             | Sf[64][68]f @46080 | Pf[64][72]h @63488 | corr/l @72704
// stride 72 halves = 36 words: ldmatrix row phases bank-distinct (4r mod 32).
// ---------------------------------------------------------------------------
#define AT_STR 72
#define AT_QOFF 0
#define AT_KOFF 9216
#define AT_VOFF 27648
#define AT_SOFF 46080
#define AT_POFF 63488
#define AT_COFF 72704
#define ATTN_SMEM_H (AT_COFF + 512)   // 73216

__global__ void __launch_bounds__(256) flash_attn_h16_kernel(
    const __half* __restrict__ Q, const __half* __restrict__ K,
    const __half* __restrict__ V, __half* __restrict__ O) {
  extern __shared__ char smc[];
  const uint32_t sb = (uint32_t)__cvta_generic_to_shared(smc);
  __half* Qf = (__half*)(smc + AT_QOFF);
  __half* Kf = (__half*)(smc + AT_KOFF);
  __half* Vf = (__half*)(smc + AT_VOFF);
  float* Sf = (float*)(smc + AT_SOFF);
  __half* Pf = (__half*)(smc + AT_POFF);
  float* corr_s = (float*)(smc + AT_COFF);
  float* l_s = corr_s + 64;

  const int qt = blockIdx.x, h = blockIdx.y, b = blockIdx.z;
  const int tid = threadIdx.x, lane = tid & 31, warp = tid >> 5;
  const int lr = lane >> 2, lc = lane & 3;
  const int mq = (warp >> 1) * 16, nq = (warp & 1) * 32;
  const int q0 = qt * 64;

  // ---- prologue: Q + KV(0) via cp.async ----
#pragma unroll
  for (int i = 0; i < 2; i++) {
    const int idx = tid + i * 256;
    const int r = idx >> 3, c = idx & 7;
    cp_async16(Qf + r * AT_STR + c * 8,
               Q + (((size_t)((b * SEQ + q0 + r) * NHEAD + h)) << 6) + c * 8);
  }
#pragma unroll
  for (int i = 0; i < 2; i++) {
    const int idx = tid + i * 256;
    const int r = idx >> 3, c = idx & 7;
    const size_t g = (((size_t)((b * SEQ + r) * NHEAD + h)) << 6) + c * 8;
    cp_async16(Kf + r * AT_STR + c * 8, K + g);
    cp_async16(Vf + r * AT_STR + c * 8, V + g);
  }
  cp_commit();
  cp_wait<0>();
  __syncthreads();

  // Q A-fragments (hoisted)
  uint32_t qa[4][4];
  {
    const int qrow = mq + (lane & 15);
#pragma unroll
    for (int ks = 0; ks < 4; ks++) {
      const uint32_t a = sb + AT_QOFF +
                         (qrow * AT_STR + ks * 16 + (lane >> 4) * 8) * 2;
      ldsm_x4(qa[ks][0], qa[ks][1], qa[ks][2], qa[ks][3], a);
    }
  }

  float oacc[4][4];
#pragma unroll
  for (int nt = 0; nt < 4; nt++)
#pragma unroll
    for (int q = 0; q < 4; q++) oacc[nt][q] = 0.f;

  const int srow = tid >> 2, sseg = tid & 3;
  float mrow = -1e30f, lrow = 0.f;

  for (int kt = 0; kt <= qt; kt++) {
    const int buf = kt & 1;
    __syncthreads();  // everyone done reading buf^1 (iteration kt-1)
    if (kt < qt) {
      const int nb = buf ^ 1;
#pragma unroll
      for (int i = 0; i < 2; i++) {
        const int idx = tid + i * 256;
        const int r = idx >> 3, c = idx & 7;
        const size_t g =
            (((size_t)((b * SEQ + (kt + 1) * 64 + r) * NHEAD + h)) << 6) + c * 8;
        cp_async16(Kf + nb * 4608 + r * AT_STR + c * 8, K + g);
        cp_async16(Vf + nb * 4608 + r * AT_STR + c * 8, V + g);
      }
      cp_commit();
      cp_wait<1>();   // KV(kt) resident; KV(kt+1) may be in flight
    } else {
      cp_wait<0>();
    }
    __syncthreads();

    const uint32_t kbase = sb + AT_KOFF + buf * 9216;
    const uint32_t vbase = sb + AT_VOFF + buf * 9216;

    // ---- S = Q @ K^T ----
    float sacc[4][4];
#pragma unroll
    for (int nt = 0; nt < 4; nt++)
#pragma unroll
      for (int q = 0; q < 4; q++) sacc[nt][q] = 0.f;
#pragma unroll
    for (int ks = 0; ks < 4; ks++) {
      uint32_t kb[4][2];
#pragma unroll
      for (int hh = 0; hh < 2; hh++) {
        const uint32_t a = kbase +
            ((nq + hh * 16 + (lane & 15)) * AT_STR + ks * 16 + (lane >> 4) * 8) * 2;
        uint32_t r0, r1, r2, r3;
        ldsm_x4(r0, r1, r2, r3, a);
        kb[2 * hh][0] = r0; kb[2 * hh + 1][0] = r1;
        kb[2 * hh][1] = r2; kb[2 * hh + 1][1] = r3;
      }
#pragma unroll
      for (int nt = 0; nt < 4; nt++)
        mma_f16(sacc[nt][0], sacc[nt][1], sacc[nt][2], sacc[nt][3],
                qa[ks][0], qa[ks][1], qa[ks][2], qa[ks][3],
                kb[nt][0], kb[nt][1]);
    }
    // scale (1/sqrt(64)) + store S to smem
#pragma unroll
    for (int nt = 0; nt < 4; nt++) {
      const int col = nq + nt * 8 + 2 * lc;
      float2 s01 = {sacc[nt][0] * 0.125f, sacc[nt][1] * 0.125f};
      float2 s23 = {sacc[nt][2] * 0.125f, sacc[nt][3] * 0.125f};
      *(float2*)(Sf + (mq + lr) * 68 + col) = s01;
      *(float2*)(Sf + (mq + 8 + lr) * 68 + col) = s23;
    }
    __syncthreads();

    // ---- online softmax: thread owns row srow, cols sseg*16..+15 ----
    float sv[16];
    {
      const float4* sp = (const float4*)(Sf + srow * 68 + sseg * 16);
      ((float4*)sv)[0] = sp[0];
      ((float4*)sv)[1] = sp[1];
      ((float4*)sv)[2] = sp[2];
      ((float4*)sv)[3] = sp[3];
    }
    if (kt == qt) {
#pragma unroll
      for (int j = 0; j < 16; j++)
        if (sseg * 16 + j > srow) sv[j] = -1e9f;
    }
    float mt2 = sv[0];
#pragma unroll
    for (int j = 1; j < 16; j++) mt2 = fmaxf(mt2, sv[j]);
    mt2 = fmaxf(mt2, __shfl_xor_sync(0xffffffffu, mt2, 1));
    mt2 = fmaxf(mt2, __shfl_xor_sync(0xffffffffu, mt2, 2));
    const float mnew = fmaxf(mrow, mt2);
    const float corr = __expf(mrow - mnew);
    float sum = 0.f;
#pragma unroll
    for (int j = 0; j < 16; j++) {
      sv[j] = __expf(sv[j] - mnew);
      sum += sv[j];
    }
    sum += __shfl_xor_sync(0xffffffffu, sum, 1);
    sum += __shfl_xor_sync(0xffffffffu, sum, 2);
    lrow = lrow * corr + sum;
    mrow = mnew;
    // write P (fp16) — 2 aligned 16B stores
    {
      uint4 u0, u1;
      __half2 t;
      t = __floats2half2_rn(sv[0], sv[1]);   u0.x = *(unsigned*)&t;
      t = __floats2half2_rn(sv[2], sv[3]);   u0.y = *(unsigned*)&t;
      t = __floats2half2_rn(sv[4], sv[5]);   u0.z = *(unsigned*)&t;
      t = __floats2half2_rn(sv[6], sv[7]);   u0.w = *(unsigned*)&t;
      t = __floats2half2_rn(sv[8], sv[9]);   u1.x = *(unsigned*)&t;
      t = __floats2half2_rn(sv[10], sv[11]); u1.y = *(unsigned*)&t;
      t = __floats2half2_rn(sv[12], sv[13]); u1.z = *(unsigned*)&t;
      t = __floats2half2_rn(sv[14], sv[15]); u1.w = *(unsigned*)&t;
      uint4* pd = (uint4*)(Pf + srow * AT_STR + sseg * 16);
      pd[0] = u0;
      pd[1] = u1;
    }
    if (sseg == 0) { corr_s[srow] = corr; l_s[srow] = lrow; }
    __syncthreads();

    // ---- rescale O, then O += P @ V ----
    const float cr0 = corr_s[mq + lr];
    const float cr1 = corr_s[mq + 8 + lr];
#pragma unroll
    for (int nt = 0; nt < 4; nt++) {
      oacc[nt][0] *= cr0; oacc[nt][1] *= cr0;
      oacc[nt][2] *= cr1; oacc[nt][3] *= cr1;
    }
#pragma unroll
    for (int ks = 0; ks < 4; ks++) {
      uint32_t pa[4];
      {
        const uint32_t a = sb + AT_POFF +
            ((mq + (lane & 15)) * AT_STR + ks * 16 + (lane >> 4) * 8) * 2;
        ldsm_x4(pa[0], pa[1], pa[2], pa[3], a);
      }
      uint32_t vb[4][2];
#pragma unroll
      for (int hh = 0; hh < 2; hh++) {
        const uint32_t a = vbase +
            ((ks * 16 + (lane & 15)) * AT_STR + nq + hh * 16 + (lane >> 4) * 8) * 2;
        uint32_t r0, r1, r2, r3;
        ldsm_x4_t(r0, r1, r2, r3, a);
        vb[2 * hh][0] = r0;     vb[2 * hh][1] = r1;
        vb[2 * hh + 1][0] = r2; vb[2 * hh + 1][1] = r3;
      }
#pragma unroll
      for (int nt = 0; nt < 4; nt++)
        mma_f16(oacc[nt][0], oacc[nt][1], oacc[nt][2], oacc[nt][3],
                pa[0], pa[1], pa[2], pa[3], vb[nt][0], vb[nt][1]);
    }
  }

  // ---- finalize ----
  const float inv0 = 1.0f / l_s[mq + lr];
  const float inv1 = 1.0f / l_s[mq + 8 + lr];
#pragma unroll
  for (int nt = 0; nt < 4; nt++) {
    const int col = nq + nt * 8 + 2 * lc;
    __half* o0 = O + (((size_t)((b * SEQ + q0 + mq + lr) * NHEAD + h)) << 6) + col;
    __half* o1 = O + (((size_t)((b * SEQ + q0 + mq + 8 + lr) * NHEAD + h)) << 6) + col;
    *(__half2*)o0 = __floats2half2_rn(oacc[nt][0] * inv0, oacc[nt][1] * inv0);
    *(__half2*)o1 = __floats2half2_rn(oacc[nt][2] * inv1, oacc[nt][3] * inv1);
  }
}

// ---------------------------------------------------------------------------
// Launch
// ---------------------------------------------------------------------------
extern "C" void kernel_launch(void* const* d_in, const int* in_sizes, int n_in,
                              void* d_out, int out_size) {
  (void)in_sizes; (void)n_in; (void)out_size;
  const float* x      = (const float*)d_in[0];
  const float* Wq     = (const float*)d_in[2];
  const float* bq     = (const float*)d_in[3];
  const float* Wk     = (const float*)d_in[4];
  const float* bk     = (const float*)d_in[5];
  const float* Wv     = (const float*)d_in[6];
  const float* bv     = (const float*)d_in[7];
  const float* Wo     = (const float*)d_in[8];
  const float* bo     = (const float*)d_in[9];
  const float* W1     = (const float*)d_in[10];
  const float* b1     = (const float*)d_in[11];
  const float* W2     = (const float*)d_in[12];
  const float* b2     = (const float*)d_in[13];
  const float* alpha1 = (const float*)d_in[14];
  const float* bias1  = (const float*)d_in[15];
  const float* alpha2 = (const float*)d_in[16];
  const float* bias2  = (const float*)d_in[17];
  float* out = (float*)d_out;

  __half *x2h, *qh, *kh, *vh, *attnh, *ffh, *wth;
  float* xmid;
  cudaGetSymbolAddress((void**)&x2h, g_x2h);
  cudaGetSymbolAddress((void**)&qh, g_qh);
  cudaGetSymbolAddress((void**)&kh, g_kh);
  cudaGetSymbolAddress((void**)&vh, g_vh);
  cudaGetSymbolAddress((void**)&attnh, g_attnh);
  cudaGetSymbolAddress((void**)&ffh, g_ffh);
  cudaGetSymbolAddress((void**)&xmid, g_xmid);
  cudaGetSymbolAddress((void**)&wth, g_wth);

  cudaFuncSetAttribute(flash_attn_h16_kernel,
                       cudaFuncAttributeMaxDynamicSharedMemorySize, ATTN_SMEM_H);
  cudaFuncSetAttribute(hgemm_kernel<1, __half>,
                       cudaFuncAttributeMaxDynamicSharedMemorySize, HGEMM_SMEM);
  cudaFuncSetAttribute(hgemm_kernel<2, float>,
                       cudaFuncAttributeMaxDynamicSharedMemorySize, HGEMM_SMEM);
  cudaFuncSetAttribute(hqkv_kernel,
                       cudaFuncAttributeMaxDynamicSharedMemorySize, HGEMM_SMEM);

  const dim3 gemm_grid(DMODEL / 128, ROWS / 128);
  const dim3 qkv_grid(DMODEL / 128, ROWS / 128, 3);

  transpose6_kernel<<<dim3(32, 32, 6), dim3(32, 8)>>>(Wq, Wk, Wv, Wo, W1, W2, wth);
  layernorm_kernel<<<ROWS, 256>>>(x, alpha1, bias1, x2h);
  hqkv_kernel<<<qkv_grid, 256, HGEMM_SMEM>>>(x2h, wth, bq, qh, bk, kh, bv, vh);
  flash_attn_h16_kernel<<<dim3(SEQ / 64, NHEAD, BATCH), 256, ATTN_SMEM_H>>>(
      qh, kh, vh, attnh);
  hgemm_kernel<2, float><<<gemm_grid, 256, HGEMM_SMEM>>>(
      attnh, wth + (size_t)3 * DMODEL * DMODEL, bo, x, xmid);
  layernorm_kernel<<<ROWS, 256>>>(xmid, alpha2, bias2, x2h);
  hgemm_kernel<1, __half><<<gemm_grid, 256, HGEMM_SMEM>>>(
      x2h, wth + (size_t)4 * DMODEL * DMODEL, b1, nullptr, ffh);
  hgemm_kernel<2, float><<<gemm_grid, 256, HGEMM_SMEM>>>(
      ffh, wth + (size_t)5 * DMODEL * DMODEL, b2, xmid, out);
}

// round 12
// speedup vs baseline: 10.9232x; 1.0858x over previous
#include <cuda_runtime.h>
#include <cuda_fp16.h>
#include <math.h>
#include <stdint.h>

// Problem constants
#define BATCH 4
#define SEQ 2048
#define DMODEL 1024
#define NHEAD 16
#define ROWS (BATCH * SEQ)   // 8192

// ---------------------------------------------------------------------------
// Scratch (device globals; no allocation allowed)
// ---------------------------------------------------------------------------
__device__ __half g_x2h[ROWS * DMODEL];
__device__ __half g_qh[ROWS * DMODEL];
__device__ __half g_kh[ROWS * DMODEL];
__device__ __half g_vh[ROWS * DMODEL];
__device__ __half g_attnh[ROWS * DMODEL];
__device__ __half g_ffh[ROWS * DMODEL];
__device__ float g_xmid[ROWS * DMODEL];
__device__ __half g_wth[6 * DMODEL * DMODEL];   // transposed fp16 weights [N][K]

// ---------------------------------------------------------------------------
// helpers
// ---------------------------------------------------------------------------
__device__ __forceinline__ void mma_f16(
    float& c0, float& c1, float& c2, float& c3,
    unsigned a0, unsigned a1, unsigned a2, unsigned a3,
    unsigned b0, unsigned b1) {
  asm("mma.sync.aligned.m16n8k16.row.col.f32.f16.f16.f32 "
      "{%0,%1,%2,%3}, {%4,%5,%6,%7}, {%8,%9}, {%0,%1,%2,%3};"
      : "+f"(c0), "+f"(c1), "+f"(c2), "+f"(c3)
      : "r"(a0), "r"(a1), "r"(a2), "r"(a3), "r"(b0), "r"(b1));
}

__device__ __forceinline__ void ldsm_x4(uint32_t& r0, uint32_t& r1,
                                        uint32_t& r2, uint32_t& r3, uint32_t a) {
  asm volatile("ldmatrix.sync.aligned.m8n8.x4.shared.b16 {%0,%1,%2,%3}, [%4];"
               : "=r"(r0), "=r"(r1), "=r"(r2), "=r"(r3) : "r"(a));
}
__device__ __forceinline__ void ldsm_x4_t(uint32_t& r0, uint32_t& r1,
                                          uint32_t& r2, uint32_t& r3, uint32_t a) {
  asm volatile("ldmatrix.sync.aligned.m8n8.x4.trans.shared.b16 {%0,%1,%2,%3}, [%4];"
               : "=r"(r0), "=r"(r1), "=r"(r2), "=r"(r3) : "r"(a));
}

__device__ __forceinline__ void cp_async16(void* smem_dst, const void* gmem_src) {
  unsigned s = (unsigned)__cvta_generic_to_shared(smem_dst);
  asm volatile("cp.async.ca.shared.global [%0], [%1], 16;\n" ::"r"(s),
               "l"(gmem_src));
}
__device__ __forceinline__ void cp_commit() {
  asm volatile("cp.async.commit_group;\n" ::);
}
template <int N>
__device__ __forceinline__ void cp_wait() {
  asm volatile("cp.async.wait_group %0;\n" ::"n"(N));
}

__device__ __forceinline__ float gelu_f(float v) {
  float t = tanhf(0.7978845608028654f * (v + 0.044715f * v * v * v));
  return 0.5f * v * (1.0f + t);
}

__device__ __forceinline__ unsigned h2u(__half2 h) { return *(unsigned*)&h; }

// ---------------------------------------------------------------------------
// LayerNorm: f32 in -> fp16 out
// ---------------------------------------------------------------------------
__global__ void __launch_bounds__(256) layernorm_kernel(
    const float* __restrict__ x, const float* __restrict__ alpha,
    const float* __restrict__ beta, __half* __restrict__ y) {
  __shared__ float red[8];
  __shared__ float bcast;
  const int row = blockIdx.x;
  const int tid = threadIdx.x;
  const float* xp = x + (size_t)row * DMODEL;

  float4 v = *(const float4*)(xp + tid * 4);
  float s = v.x + v.y + v.z + v.w;
#pragma unroll
  for (int o = 16; o; o >>= 1) s += __shfl_xor_sync(0xffffffffu, s, o);
  if ((tid & 31) == 0) red[tid >> 5] = s;
  __syncthreads();
  if (tid == 0) {
    float t = 0.f;
#pragma unroll
    for (int i = 0; i < 8; i++) t += red[i];
    bcast = t;
  }
  __syncthreads();
  const float mean = bcast * (1.0f / (float)DMODEL);
  __syncthreads();

  const float dx = v.x - mean, dy = v.y - mean, dz = v.z - mean, dw = v.w - mean;
  float sq = dx * dx + dy * dy + dz * dz + dw * dw;
#pragma unroll
  for (int o = 16; o; o >>= 1) sq += __shfl_xor_sync(0xffffffffu, sq, o);
  if ((tid & 31) == 0) red[tid >> 5] = sq;
  __syncthreads();
  if (tid == 0) {
    float t = 0.f;
#pragma unroll
    for (int i = 0; i < 8; i++) t += red[i];
    bcast = t;
  }
  __syncthreads();
  const float var = bcast * (1.0f / (float)(DMODEL - 1));
  const float sc = 1.0f / (sqrtf(var) + 1e-6f);

  const float4 a4 = *(const float4*)(alpha + tid * 4);
  const float4 b4 = *(const float4*)(beta + tid * 4);
  __half2 h01 = __floats2half2_rn(a4.x * dx * sc + b4.x, a4.y * dy * sc + b4.y);
  __half2 h23 = __floats2half2_rn(a4.z * dz * sc + b4.z, a4.w * dw * sc + b4.w);
  uint2 u = {h2u(h01), h2u(h23)};
  *(uint2*)(y + (size_t)row * DMODEL + tid * 4) = u;
}

// ---------------------------------------------------------------------------
// Weight transpose prepass: Wt[n][k] = (half)W[k][n]
// ---------------------------------------------------------------------------
__global__ void __launch_bounds__(256) transpose6_kernel(
    const float* __restrict__ Wq, const float* __restrict__ Wk,
    const float* __restrict__ Wv, const float* __restrict__ Wo,
    const float* __restrict__ W1, const float* __restrict__ W2,
    __half* __restrict__ wt) {
  const float* src;
  switch (blockIdx.z) {
    case 0: src = Wq; break;
    case 1: src = Wk; break;
    case 2: src = Wv; break;
    case 3: src = Wo; break;
    case 4: src = W1; break;
    default: src = W2; break;
  }
  __half* dst = wt + (size_t)blockIdx.z * DMODEL * DMODEL;
  __shared__ float tl[32][33];
  const int tx = threadIdx.x, ty = threadIdx.y;
  const int x = blockIdx.x * 32 + tx;
  const int y = blockIdx.y * 32 + ty;
#pragma unroll
  for (int i = 0; i < 32; i += 8)
    tl[ty + i][tx] = src[(size_t)(y + i) * DMODEL + x];
  __syncthreads();
  const int x2 = blockIdx.y * 32 + tx;
  const int y2 = blockIdx.x * 32 + ty;
#pragma unroll
  for (int i = 0; i < 32; i += 8)
    dst[(size_t)(y2 + i) * DMODEL + x2] = __float2half_rn(tl[tx][ty + i]);
}

// ---------------------------------------------------------------------------
// fp16 TC GEMM (unchanged, proven)
// ---------------------------------------------------------------------------
#define HBK 32
#define HROWB 80
#define HA_BYTES (128 * HROWB)
#define HSTAGE_BYTES (2 * HA_BYTES)
#define HNSTAGE 4
#define HGEMM_SMEM (HSTAGE_BYTES * HNSTAGE)

template <int EPI, typename OutT>
__device__ __forceinline__ void hgemm_body(
    const __half* __restrict__ A, const __half* __restrict__ Bt,
    const float* __restrict__ bias, const float* __restrict__ res,
    OutT* __restrict__ C) {
  extern __shared__ char smc[];
  const int tid = threadIdx.x;
  const int cRow = blockIdx.y, cCol = blockIdx.x;
  const int lane = tid & 31, warp = tid >> 5;
  const int lr = lane >> 2, lc = lane & 3;
  const int m0 = (warp & 1) * 64;
  const int n0 = (warp >> 1) * 32;

  const int row = tid >> 2;
  const int ch = tid & 3;

  const __half* Ap = A + (size_t)(cRow * 128 + row) * DMODEL + ch * 8;
  const __half* Bp = Bt + (size_t)(cCol * 128 + row) * DMODEL + ch * 8;

  float acc[4][4][4];
#pragma unroll
  for (int i = 0; i < 4; i++)
#pragma unroll
    for (int j = 0; j < 4; j++)
#pragma unroll
      for (int q = 0; q < 4; q++) acc[i][j][q] = 0.f;

  const int NT = DMODEL / HBK;

  auto issue = [&](int s, int t) {
    char* base = smc + s * HSTAGE_BYTES;
    const int k0 = t * HBK;
    cp_async16(base + row * HROWB + ch * 16, Ap + k0);
    cp_async16(base + (row + 64) * HROWB + ch * 16, Ap + (size_t)64 * DMODEL + k0);
    cp_async16(base + HA_BYTES + row * HROWB + ch * 16, Bp + k0);
    cp_async16(base + HA_BYTES + (row + 64) * HROWB + ch * 16,
               Bp + (size_t)64 * DMODEL + k0);
  };

#pragma unroll
  for (int s = 0; s < HNSTAGE - 1; s++) { issue(s, s); cp_commit(); }

  for (int t = 0; t < NT; t++) {
    cp_wait<HNSTAGE - 2>();
    __syncthreads();

    const char* base = smc + (t & (HNSTAGE - 1)) * HSTAGE_BYTES;
    const unsigned* Au = (const unsigned*)base;
    const unsigned* Bu = (const unsigned*)(base + HA_BYTES);

#pragma unroll
    for (int ks = 0; ks < 2; ks++) {
      const int kb = ks * 8;
      unsigned af[4][4], bf[4][2];
#pragma unroll
      for (int mt = 0; mt < 4; mt++) {
        const int m = m0 + mt * 16 + lr;
        af[mt][0] = Au[m * 20 + kb + lc];
        af[mt][1] = Au[(m + 8) * 20 + kb + lc];
        af[mt][2] = Au[m * 20 + kb + 4 + lc];
        af[mt][3] = Au[(m + 8) * 20 + kb + 4 + lc];
      }
#pragma unroll
      for (int nt = 0; nt < 4; nt++) {
        const int n = n0 + nt * 8 + lr;
        bf[nt][0] = Bu[n * 20 + kb + lc];
        bf[nt][1] = Bu[n * 20 + kb + 4 + lc];
      }
#pragma unroll
      for (int mt = 0; mt < 4; mt++)
#pragma unroll
        for (int nt = 0; nt < 4; nt++)
          mma_f16(acc[mt][nt][0], acc[mt][nt][1], acc[mt][nt][2], acc[mt][nt][3],
                  af[mt][0], af[mt][1], af[mt][2], af[mt][3],
                  bf[nt][0], bf[nt][1]);
    }

    if (t + HNSTAGE - 1 < NT)
      issue((t + HNSTAGE - 1) & (HNSTAGE - 1), t + HNSTAGE - 1);
    cp_commit();
  }

#pragma unroll
  for (int mt = 0; mt < 4; mt++) {
    const int r0 = cRow * 128 + m0 + mt * 16 + lr;
#pragma unroll
    for (int nt = 0; nt < 4; nt++) {
      const int col = cCol * 128 + n0 + nt * 8 + 2 * lc;
      const float bx = bias[col], by = bias[col + 1];
      float v0 = acc[mt][nt][0] + bx, v1 = acc[mt][nt][1] + by;
      float v2 = acc[mt][nt][2] + bx, v3 = acc[mt][nt][3] + by;
      if (EPI == 1) { v0 = gelu_f(v0); v1 = gelu_f(v1); v2 = gelu_f(v2); v3 = gelu_f(v3); }
      if (EPI == 2) {
        const float2 r4a = *(const float2*)(res + (size_t)r0 * DMODEL + col);
        const float2 r4b = *(const float2*)(res + (size_t)(r0 + 8) * DMODEL + col);
        v0 += r4a.x; v1 += r4a.y; v2 += r4b.x; v3 += r4b.y;
      }
      if (sizeof(OutT) == 2) {
        __half2 h0 = __floats2half2_rn(v0, v1);
        __half2 h1 = __floats2half2_rn(v2, v3);
        *(__half2*)((__half*)C + (size_t)r0 * DMODEL + col) = h0;
        *(__half2*)((__half*)C + (size_t)(r0 + 8) * DMODEL + col) = h1;
      } else {
        float2 o0 = {v0, v1}, o1 = {v2, v3};
        *(float2*)((float*)C + (size_t)r0 * DMODEL + col) = o0;
        *(float2*)((float*)C + (size_t)(r0 + 8) * DMODEL + col) = o1;
      }
    }
  }
}

template <int EPI, typename OutT>
__global__ void __launch_bounds__(256) hgemm_kernel(
    const __half* __restrict__ A, const __half* __restrict__ Bt,
    const float* __restrict__ bias, const float* __restrict__ res,
    OutT* __restrict__ C) {
  hgemm_body<EPI, OutT>(A, Bt, bias, res, C);
}

__global__ void __launch_bounds__(256) hqkv_kernel(
    const __half* __restrict__ A, const __half* __restrict__ wt,
    const float* __restrict__ bq, __half* __restrict__ q,
    const float* __restrict__ bk, __half* __restrict__ k,
    const float* __restrict__ bv, __half* __restrict__ v) {
  const __half* Bt;
  const float* bias;
  __half* C;
  if (blockIdx.z == 0)      { Bt = wt;                               bias = bq; C = q; }
  else if (blockIdx.z == 1) { Bt = wt + (size_t)DMODEL * DMODEL;     bias = bk; C = k; }
  else                      { Bt = wt + (size_t)2 * DMODEL * DMODEL; bias = bv; C = v; }
  hgemm_body<0, __half>(A, Bt, bias, nullptr, C);
}

// ---------------------------------------------------------------------------
// Flash attention (causal), fp16 mma, REGISTER-RESIDENT softmax.
// 64q x 64k tile, 8 warps. Warp pair p=warp>>1 owns rows p*16; within pair,
// khalf=warp&1 owns k-cols khalf*32. S accumulator converts in-register to
// the PV A-fragment (layouts coincide). Cross-warp: only per-row max/sum
// (1KB stats) + one partial-O combine at epilogue (k-split PV).
// smem: Qf[64][72]h @0 | Kf[2][64][72]h @9216 | Vf[2][64][72]h @27648
//     | stats @46080 (max[64][2], sum[64][2]) | epi buf overlaps Qf/Kf.
// ---------------------------------------------------------------------------
#define AT_STR 72
#define AT_QOFF 0
#define AT_KOFF 9216
#define AT_VOFF 27648
#define AT_STOFF 46080
#define ATTN_SMEM_H (AT_STOFF + 1024 + 128)   // 47232

__global__ void __launch_bounds__(256) flash_attn_h16_kernel(
    const __half* __restrict__ Q, const __half* __restrict__ K,
    const __half* __restrict__ V, __half* __restrict__ O) {
  extern __shared__ char smc[];
  const uint32_t sb = (uint32_t)__cvta_generic_to_shared(smc);
  __half* Qf = (__half*)(smc + AT_QOFF);
  __half* Kf = (__half*)(smc + AT_KOFF);
  __half* Vf = (__half*)(smc + AT_VOFF);
  float* stat_max = (float*)(smc + AT_STOFF);        // [64][2]
  float* stat_sum = (float*)(smc + AT_STOFF + 512);  // [64][2]
  float* ebuf = (float*)smc;                          // epilogue, overlaps Q/K

  const int qt = blockIdx.x, h = blockIdx.y, b = blockIdx.z;
  const int tid = threadIdx.x, lane = tid & 31, warp = tid >> 5;
  const int lr = lane >> 2, lc = lane & 3;
  const int pair = warp >> 1, khalf = warp & 1;
  const int mq = pair * 16, nq = khalf * 32;
  const int q0 = qt * 64;

  // ---- prologue: Q + KV(0) via cp.async ----
#pragma unroll
  for (int i = 0; i < 2; i++) {
    const int idx = tid + i * 256;
    const int r = idx >> 3, c = idx & 7;
    cp_async16(Qf + r * AT_STR + c * 8,
               Q + (((size_t)((b * SEQ + q0 + r) * NHEAD + h)) << 6) + c * 8);
  }
#pragma unroll
  for (int i = 0; i < 2; i++) {
    const int idx = tid + i * 256;
    const int r = idx >> 3, c = idx & 7;
    const size_t g = (((size_t)((b * SEQ + r) * NHEAD + h)) << 6) + c * 8;
    cp_async16(Kf + r * AT_STR + c * 8, K + g);
    cp_async16(Vf + r * AT_STR + c * 8, V + g);
  }
  cp_commit();
  cp_wait<0>();
  __syncthreads();

  // Q A-fragments (hoisted)
  uint32_t qa[4][4];
  {
    const int qrow = mq + (lane & 15);
#pragma unroll
    for (int ks = 0; ks < 4; ks++) {
      const uint32_t a = sb + AT_QOFF +
                         (qrow * AT_STR + ks * 16 + (lane >> 4) * 8) * 2;
      ldsm_x4(qa[ks][0], qa[ks][1], qa[ks][2], qa[ks][3], a);
    }
  }

  float oacc[8][4];
#pragma unroll
  for (int nt = 0; nt < 8; nt++)
#pragma unroll
    for (int q = 0; q < 4; q++) oacc[nt][q] = 0.f;

  const int r0 = mq + lr, r1 = mq + 8 + lr;   // rows this thread owns
  float mrow0 = -1e30f, mrow1 = -1e30f, lrow0 = 0.f, lrow1 = 0.f;

  for (int kt = 0; kt <= qt; kt++) {
    const int buf = kt & 1;
    __syncthreads();  // prev iter reads of KV[buf^1] & stats done
    if (kt < qt) {
      const int nb = buf ^ 1;
#pragma unroll
      for (int i = 0; i < 2; i++) {
        const int idx = tid + i * 256;
        const int r = idx >> 3, c = idx & 7;
        const size_t g =
            (((size_t)((b * SEQ + (kt + 1) * 64 + r) * NHEAD + h)) << 6) + c * 8;
        cp_async16(Kf + nb * 4608 + r * AT_STR + c * 8, K + g);
        cp_async16(Vf + nb * 4608 + r * AT_STR + c * 8, V + g);
      }
      cp_commit();
      cp_wait<1>();
    } else {
      cp_wait<0>();
    }
    __syncthreads();

    const uint32_t kbase = sb + AT_KOFF + buf * 9216;
    const uint32_t vbase = sb + AT_VOFF + buf * 9216;

    // ---- S = Q @ K^T (rows mq..mq+15, cols nq..nq+31) ----
    float sacc[4][4];
#pragma unroll
    for (int nt = 0; nt < 4; nt++)
#pragma unroll
      for (int q = 0; q < 4; q++) sacc[nt][q] = 0.f;
#pragma unroll
    for (int ks = 0; ks < 4; ks++) {
      uint32_t kb[4][2];
#pragma unroll
      for (int hh = 0; hh < 2; hh++) {
        const uint32_t a = kbase +
            ((nq + hh * 16 + (lane & 15)) * AT_STR + ks * 16 + (lane >> 4) * 8) * 2;
        uint32_t t0, t1, t2, t3;
        ldsm_x4(t0, t1, t2, t3, a);
        kb[2 * hh][0] = t0; kb[2 * hh + 1][0] = t1;
        kb[2 * hh][1] = t2; kb[2 * hh + 1][1] = t3;
      }
#pragma unroll
      for (int nt = 0; nt < 4; nt++)
        mma_f16(sacc[nt][0], sacc[nt][1], sacc[nt][2], sacc[nt][3],
                qa[ks][0], qa[ks][1], qa[ks][2], qa[ks][3],
                kb[nt][0], kb[nt][1]);
    }

    // ---- scale + causal mask (in registers) ----
#pragma unroll
    for (int nt = 0; nt < 4; nt++)
#pragma unroll
      for (int q = 0; q < 4; q++) sacc[nt][q] *= 0.125f;
    if (kt == qt) {
#pragma unroll
      for (int nt = 0; nt < 4; nt++) {
        const int cl = nq + nt * 8 + 2 * lc;
        if (cl > r0) sacc[nt][0] = -1e9f;
        if (cl + 1 > r0) sacc[nt][1] = -1e9f;
        if (cl > r1) sacc[nt][2] = -1e9f;
        if (cl + 1 > r1) sacc[nt][3] = -1e9f;
      }
    }

    // ---- row max: thread-local -> quad shfl -> cross-warp via stats ----
    float tm0 = sacc[0][0], tm1 = sacc[0][2];
#pragma unroll
    for (int nt = 0; nt < 4; nt++) {
      tm0 = fmaxf(tm0, fmaxf(sacc[nt][0], sacc[nt][1]));
      tm1 = fmaxf(tm1, fmaxf(sacc[nt][2], sacc[nt][3]));
    }
    tm0 = fmaxf(tm0, __shfl_xor_sync(0xffffffffu, tm0, 1));
    tm0 = fmaxf(tm0, __shfl_xor_sync(0xffffffffu, tm0, 2));
    tm1 = fmaxf(tm1, __shfl_xor_sync(0xffffffffu, tm1, 1));
    tm1 = fmaxf(tm1, __shfl_xor_sync(0xffffffffu, tm1, 2));
    if (lc == 0) {
      stat_max[r0 * 2 + khalf] = tm0;
      stat_max[r1 * 2 + khalf] = tm1;
    }
    __syncthreads();
    const float mt0 = fmaxf(stat_max[r0 * 2], stat_max[r0 * 2 + 1]);
    const float mt1 = fmaxf(stat_max[r1 * 2], stat_max[r1 * 2 + 1]);
    const float mnew0 = fmaxf(mrow0, mt0), mnew1 = fmaxf(mrow1, mt1);
    const float corr0 = __expf(mrow0 - mnew0), corr1 = __expf(mrow1 - mnew1);

    // ---- exp in registers; pack P A-fragments directly ----
    float ev[4][4];
    float ps0 = 0.f, ps1 = 0.f;
#pragma unroll
    for (int nt = 0; nt < 4; nt++) {
      ev[nt][0] = __expf(sacc[nt][0] - mnew0);
      ev[nt][1] = __expf(sacc[nt][1] - mnew0);
      ev[nt][2] = __expf(sacc[nt][2] - mnew1);
      ev[nt][3] = __expf(sacc[nt][3] - mnew1);
      ps0 += ev[nt][0] + ev[nt][1];
      ps1 += ev[nt][2] + ev[nt][3];
    }
    ps0 += __shfl_xor_sync(0xffffffffu, ps0, 1);
    ps0 += __shfl_xor_sync(0xffffffffu, ps0, 2);
    ps1 += __shfl_xor_sync(0xffffffffu, ps1, 1);
    ps1 += __shfl_xor_sync(0xffffffffu, ps1, 2);
    if (lc == 0) {
      stat_sum[r0 * 2 + khalf] = ps0;
      stat_sum[r1 * 2 + khalf] = ps1;
    }
    uint32_t pa[2][4];
#pragma unroll
    for (int ks2 = 0; ks2 < 2; ks2++) {
      pa[ks2][0] = h2u(__floats2half2_rn(ev[2 * ks2][0], ev[2 * ks2][1]));
      pa[ks2][1] = h2u(__floats2half2_rn(ev[2 * ks2][2], ev[2 * ks2][3]));
      pa[ks2][2] = h2u(__floats2half2_rn(ev[2 * ks2 + 1][0], ev[2 * ks2 + 1][1]));
      pa[ks2][3] = h2u(__floats2half2_rn(ev[2 * ks2 + 1][2], ev[2 * ks2 + 1][3]));
    }
    __syncthreads();
    lrow0 = lrow0 * corr0 + (stat_sum[r0 * 2] + stat_sum[r0 * 2 + 1]);
    lrow1 = lrow1 * corr1 + (stat_sum[r1 * 2] + stat_sum[r1 * 2 + 1]);
    mrow0 = mnew0; mrow1 = mnew1;

    // ---- rescale partial O; O += P @ V over this warp's 32 keys ----
#pragma unroll
    for (int nt = 0; nt < 8; nt++) {
      oacc[nt][0] *= corr0; oacc[nt][1] *= corr0;
      oacc[nt][2] *= corr1; oacc[nt][3] *= corr1;
    }
#pragma unroll
    for (int ks2 = 0; ks2 < 2; ks2++) {
      uint32_t vb[8][2];
#pragma unroll
      for (int hh = 0; hh < 4; hh++) {
        const uint32_t a = vbase +
            ((nq + ks2 * 16 + (lane & 15)) * AT_STR + hh * 16 + (lane >> 4) * 8) * 2;
        uint32_t t0, t1, t2, t3;
        ldsm_x4_t(t0, t1, t2, t3, a);
        vb[2 * hh][0] = t0;     vb[2 * hh][1] = t1;
        vb[2 * hh + 1][0] = t2; vb[2 * hh + 1][1] = t3;
      }
#pragma unroll
      for (int nt = 0; nt < 8; nt++)
        mma_f16(oacc[nt][0], oacc[nt][1], oacc[nt][2], oacc[nt][3],
                pa[ks2][0], pa[ks2][1], pa[ks2][2], pa[ks2][3],
                vb[nt][0], vb[nt][1]);
    }
  }

  // ---- epilogue: combine k-split partials across warp pair ----
  __syncthreads();  // all PV reads done; safe to reuse Q/K smem
  if (khalf == 1) {
#pragma unroll
    for (int nt = 0; nt < 8; nt++) {
      const int col = nt * 8 + 2 * lc;
      *(float2*)&ebuf[(mq + lr) * 68 + col] =
          make_float2(oacc[nt][0], oacc[nt][1]);
      *(float2*)&ebuf[(mq + 8 + lr) * 68 + col] =
          make_float2(oacc[nt][2], oacc[nt][3]);
    }
  }
  __syncthreads();
  if (khalf == 0) {
    const float inv0 = 1.0f / lrow0, inv1 = 1.0f / lrow1;
#pragma unroll
    for (int nt = 0; nt < 8; nt++) {
      const int col = nt * 8 + 2 * lc;
      const float2 p0 = *(const float2*)&ebuf[(mq + lr) * 68 + col];
      const float2 p1 = *(const float2*)&ebuf[(mq + 8 + lr) * 68 + col];
      __half* o0 = O + (((size_t)((b * SEQ + q0 + mq + lr) * NHEAD + h)) << 6) + col;
      __half* o1 =
          O + (((size_t)((b * SEQ + q0 + mq + 8 + lr) * NHEAD + h)) << 6) + col;
      *(__half2*)o0 = __floats2half2_rn((oacc[nt][0] + p0.x) * inv0,
                                        (oacc[nt][1] + p0.y) * inv0);
      *(__half2*)o1 = __floats2half2_rn((oacc[nt][2] + p1.x) * inv1,
                                        (oacc[nt][3] + p1.y) * inv1);
    }
  }
}

// ---------------------------------------------------------------------------
// Launch
// ---------------------------------------------------------------------------
extern "C" void kernel_launch(void* const* d_in, const int* in_sizes, int n_in,
                              void* d_out, int out_size) {
  (void)in_sizes; (void)n_in; (void)out_size;
  const float* x      = (const float*)d_in[0];
  const float* Wq     = (const float*)d_in[2];
  const float* bq     = (const float*)d_in[3];
  const float* Wk     = (const float*)d_in[4];
  const float* bk     = (const float*)d_in[5];
  const float* Wv     = (const float*)d_in[6];
  const float* bv     = (const float*)d_in[7];
  const float* Wo     = (const float*)d_in[8];
  const float* bo     = (const float*)d_in[9];
  const float* W1     = (const float*)d_in[10];
  const float* b1     = (const float*)d_in[11];
  const float* W2     = (const float*)d_in[12];
  const float* b2     = (const float*)d_in[13];
  const float* alpha1 = (const float*)d_in[14];
  const float* bias1  = (const float*)d_in[15];
  const float* alpha2 = (const float*)d_in[16];
  const float* bias2  = (const float*)d_in[17];
  float* out = (float*)d_out;

  __half *x2h, *qh, *kh, *vh, *attnh, *ffh, *wth;
  float* xmid;
  cudaGetSymbolAddress((void**)&x2h, g_x2h);
  cudaGetSymbolAddress((void**)&qh, g_qh);
  cudaGetSymbolAddress((void**)&kh, g_kh);
  cudaGetSymbolAddress((void**)&vh, g_vh);
  cudaGetSymbolAddress((void**)&attnh, g_attnh);
  cudaGetSymbolAddress((void**)&ffh, g_ffh);
  cudaGetSymbolAddress((void**)&xmid, g_xmid);
  cudaGetSymbolAddress((void**)&wth, g_wth);

  cudaFuncSetAttribute(flash_attn_h16_kernel,
                       cudaFuncAttributeMaxDynamicSharedMemorySize, ATTN_SMEM_H);
  cudaFuncSetAttribute(hgemm_kernel<1, __half>,
                       cudaFuncAttributeMaxDynamicSharedMemorySize, HGEMM_SMEM);
  cudaFuncSetAttribute(hgemm_kernel<2, float>,
                       cudaFuncAttributeMaxDynamicSharedMemorySize, HGEMM_SMEM);
  cudaFuncSetAttribute(hqkv_kernel,
                       cudaFuncAttributeMaxDynamicSharedMemorySize, HGEMM_SMEM);

  const dim3 gemm_grid(DMODEL / 128, ROWS / 128);
  const dim3 qkv_grid(DMODEL / 128, ROWS / 128, 3);

  transpose6_kernel<<<dim3(32, 32, 6), dim3(32, 8)>>>(Wq, Wk, Wv, Wo, W1, W2, wth);
  layernorm_kernel<<<ROWS, 256>>>(x, alpha1, bias1, x2h);
  hqkv_kernel<<<qkv_grid, 256, HGEMM_SMEM>>>(x2h, wth, bq, qh, bk, kh, bv, vh);
  flash_attn_h16_kernel<<<dim3(SEQ / 64, NHEAD, BATCH), 256, ATTN_SMEM_H>>>(
      qh, kh, vh, attnh);
  hgemm_kernel<2, float><<<gemm_grid, 256, HGEMM_SMEM>>>(
      attnh, wth + (size_t)3 * DMODEL * DMODEL, bo, x, xmid);
  layernorm_kernel<<<ROWS, 256>>>(xmid, alpha2, bias2, x2h);
  hgemm_kernel<1, __half><<<gemm_grid, 256, HGEMM_SMEM>>>(
      x2h, wth + (size_t)4 * DMODEL * DMODEL, b1, nullptr, ffh);
  hgemm_kernel<2, float><<<gemm_grid, 256, HGEMM_SMEM>>>(
      ffh, wth + (size_t)5 * DMODEL * DMODEL, b2, xmid, out);
}